// round 10
// baseline (speedup 1.0000x reference)
#include <cuda_runtime.h>
#include <math.h>
#include <stdint.h>

#define NN 8000
#define NS 4000
#define DD 64
#define HH 128
#define EK 15
#define KK 16
#define MAXDEG 256
#define NPAIR 120
#define OUTM (NS*NPAIR)

// ---------------- device scratch (static, no dynamic allocation) ----------------
__device__ __align__(16) float g_adj[NS*NS];          // 64 MB dense symmetric adjacency
__device__ unsigned long long g_key[NN];
__device__ int   g_sel[NS];
__device__ __align__(16) float g_sx[NS*DD];
__device__ __align__(16) float g_sp[NS*4];            // x,y,z,sq
__device__ float g_G[NS*HH];
__device__ int   g_nbr[NS*EK];
__device__ int   g_deg[NS];
__device__ __align__(16) int   g_nzc[NS*MAXDEG];
__device__ __align__(16) float g_nzv[NS*MAXDEG];
__device__ float g_sqadj[NS];
__device__ int   g_knn[NS*KK];

__device__ __forceinline__ unsigned ord_f(float f){
    unsigned u = __float_as_uint(f);
    return (u & 0x80000000u) ? ~u : (u | 0x80000000u);   // ascending-float -> ascending-uint
}

// ---- XLA/Eigen fast tanh (f32), bit-exact replication ----
__device__ __forceinline__ float tanh_xla(float x){
    float ax = fabsf(x);
    if (ax < 0.0004f) return x;                           // XLA kCanUseApprox shortcut
    float xc = fminf(fmaxf(x, -7.90531110763549805f), 7.90531110763549805f);
    float x2 = __fmul_rn(xc, xc);
    float p = __fmaf_rn(x2, -2.76076847742355e-16f, 2.00018790482477e-13f);
    p = __fmaf_rn(x2, p, -8.60467152213735e-11f);
    p = __fmaf_rn(x2, p,  5.12229709037114e-08f);
    p = __fmaf_rn(x2, p,  1.48572235717979e-05f);
    p = __fmaf_rn(x2, p,  6.37261928875436e-04f);
    p = __fmaf_rn(x2, p,  4.89352455891786e-03f);
    p = __fmul_rn(p, xc);
    float q = __fmaf_rn(x2, 1.19825839466702e-06f, 1.18534705686654e-04f);
    q = __fmaf_rn(x2, q, 2.26843463243900e-03f);
    q = __fmaf_rn(x2, q, 4.89352518554385e-03f);
    return __fdiv_rn(p, q);
}
// XLA logistic expansion: 0.5 + 0.5 * tanh(0.5 * x)
__device__ __forceinline__ float sigmoid_xla(float v){
    return __fadd_rn(0.5f, __fmul_rn(0.5f, tanh_xla(__fmul_rn(0.5f, v))));
}
// XLA row-reduction warp tail: shfl_down butterfly 16..1, result in lane 0
__device__ __forceinline__ float warp_red_xla(float s){
    #pragma unroll
    for (int o = 16; o > 0; o >>= 1)
        s = __fadd_rn(s, __shfl_down_sync(0xffffffffu, s, o));
    return s;
}

// ---------------- K0: zero adjacency ----------------
__global__ void __launch_bounds__(256) k_zero_adj(){
    float4 z = make_float4(0.f,0.f,0.f,0.f);
    float4* p = reinterpret_cast<float4*>(g_adj);
    const int n4 = (NS*NS)/4;
    for (int i = blockIdx.x*blockDim.x + threadIdx.x; i < n4; i += gridDim.x*blockDim.x)
        p[i] = z;
}

// ---------------- K1: probs = sigmoid_xla(relu(x@W1+b1)@w2), warp per node ----------------
// h chain: cublas/Eigen-style ascending-k fma from 0, +bias, relu.
// h@w2: strength-reduced mult+row-reduce: lane partial k=lane+32j (rounded products,
// sequential adds), then shfl butterfly.
__global__ void __launch_bounds__(128) k_probs(const float* __restrict__ x,
                        const float* __restrict__ W1,
                        const float* __restrict__ b1, const float* __restrict__ w2){
    __shared__ float xs[4][DD];
    int warp = threadIdx.x >> 5, lane = threadIdx.x & 31;
    int n = blockIdx.x*4 + warp;                // 8000 nodes, 4 warps/block, grid=2000
    xs[warp][lane]      = x[n*DD + lane];
    xs[warp][lane + 32] = x[n*DD + lane + 32];
    __syncwarp();
    float s = 0.f;
    #pragma unroll
    for (int j = 0; j < 4; j++){
        int k = lane + 32*j;
        float h = 0.f;
        #pragma unroll
        for (int d = 0; d < DD; d++) h = __fmaf_rn(xs[warp][d], W1[d*HH + k], h);
        h = fmaxf(__fadd_rn(h, b1[k]), 0.f);
        float m = __fmul_rn(h, w2[k]);
        s = __fadd_rn(s, m);                    // sequential ascending-j adds
    }
    s = warp_red_xla(s);
    if (lane == 0){
        float p = sigmoid_xla(s);
        g_key[n] = ((unsigned long long)ord_f(p) << 32) | (unsigned)(NN - 1 - n); // tie->lower n
    }
}

// ---------------- K2: exact ranking (descending) -> selected order ----------------
__global__ void __launch_bounds__(256) k_rank(){
    __shared__ unsigned long long sk[256];
    int n = blockIdx.x*256 + threadIdx.x;
    unsigned long long my = (n < NN) ? g_key[n] : 0ULL;
    int cnt = 0;
    for (int base = 0; base < NN; base += 256){
        int idx = base + threadIdx.x;
        sk[threadIdx.x] = (idx < NN) ? g_key[idx] : 0ULL;
        __syncthreads();
        int lim = min(256, NN - base);
        for (int k = 0; k < lim; k++) cnt += (sk[k] > my) ? 1 : 0;
        __syncthreads();
    }
    if (n < NN && cnt < NS) g_sel[cnt] = n;
}

// ---------------- K3: gather sx/sp, pos norms, G = [sx,sp] @ Wf1 (value-only) ----------------
__global__ void __launch_bounds__(HH) k_gather(const float* __restrict__ x,
                         const float* __restrict__ pos,
                         const float* __restrict__ Wf1){
    __shared__ float xs[DD];
    __shared__ float ps[3];
    int r = blockIdx.x, t = threadIdx.x;       // 128 threads
    int i = g_sel[r];
    if (t < DD){ float v = x[i*DD + t]; xs[t] = v; g_sx[r*DD + t] = v; }
    if (t < 3){ float v = pos[i*3 + t]; ps[t] = v; g_sp[r*4 + t] = v; }
    __syncthreads();
    if (t == 0){
        // sq = (x^2 + y^2) + z^2, squares rounded separately (square-then-reduce, NO fma)
        float sq = __fadd_rn(__fadd_rn(__fmul_rn(ps[0],ps[0]), __fmul_rn(ps[1],ps[1])),
                             __fmul_rn(ps[2],ps[2]));
        g_sp[r*4 + 3] = sq;
    }
    float g = 0.f;
    #pragma unroll
    for (int d = 0; d < DD; d++) g = fmaf(xs[d], Wf1[d*HH + t], g);
    #pragma unroll
    for (int c = 0; c < 3; c++)  g = fmaf(ps[c], Wf1[(DD + c)*HH + t], g);
    g_G[r*HH + t] = g;
}

// ---------------- K4: 15-NN over positions (ascending-k fma chain, exact top_k) ----------------
__global__ void __launch_bounds__(128) k_knn_pos(){
    __shared__ float4 tile[128];
    int row = blockIdx.x*blockDim.x + threadIdx.x;
    bool act = row < NS;
    float px=0.f, py=0.f, pz=0.f, sqi=0.f;
    if (act){
        float4 m = *reinterpret_cast<const float4*>(&g_sp[row*4]);
        px = m.x; py = m.y; pz = m.z; sqi = m.w;
    }
    float bd[EK]; int bi[EK];
    #pragma unroll
    for (int s = 0; s < EK; s++){ bd[s] = 3.4e38f; bi[s] = -1; }
    for (int base = 0; base < NS; base += 128){
        int c = base + threadIdx.x;
        if (c < NS) tile[threadIdx.x] = *reinterpret_cast<const float4*>(&g_sp[c*4]);
        __syncthreads();
        int lim = min(128, NS - base);
        if (act){
            for (int k = 0; k < lim; k++){
                int cidx = base + k;
                if (cidx == row) continue;
                float4 q = tile[k];
                // acc=0; fma k=0,1,2  ->  fma(z, q.z, fma(y, q.y, round(x*q.x)))
                float dot = __fmaf_rn(pz, q.z, __fmaf_rn(py, q.y, __fmul_rn(px, q.x)));
                float d2  = __fsub_rn(__fadd_rn(sqi, q.w), __fmul_rn(2.f, dot));
                if (d2 < bd[EK-1]){                        // strict <: ties -> lower idx kept
                    bd[EK-1] = d2; bi[EK-1] = cidx;
                    #pragma unroll
                    for (int s = EK-1; s > 0; s--){
                        if (bd[s] < bd[s-1]){
                            float tv = bd[s]; bd[s] = bd[s-1]; bd[s-1] = tv;
                            int   ti = bi[s]; bi[s] = bi[s-1]; bi[s-1] = ti;
                        }
                    }
                }
            }
        }
        __syncthreads();
    }
    if (act){
        #pragma unroll
        for (int s = 0; s < EK; s++) g_nbr[row*EK + s] = bi[s];
    }
}

// ---------------- K5: edge probs, warp per edge (XLA mult+row-reduce shape) ----------------
__global__ void __launch_bounds__(256) k_edges(const float* __restrict__ we){
    int e = blockIdx.x*8 + (threadIdx.x >> 5);
    int lane = threadIdx.x & 31;
    if (e >= NS*EK) return;
    int i = e / EK;
    int j = g_nbr[e];
    const float* a = &g_sx[i*DD];
    const float* b = &g_sx[j*DD];
    // z_k = round(a_k*b_k); m_k = round(z_k*w_k); lane partial = m_lane + m_{lane+32}
    float m0 = __fmul_rn(__fmul_rn(a[lane],      b[lane]),      we[lane]);
    float m1 = __fmul_rn(__fmul_rn(a[lane + 32], b[lane + 32]), we[lane + 32]);
    float s  = __fadd_rn(m0, m1);
    s = warp_red_xla(s);
    if (lane == 0){
        float ep = sigmoid_xla(s);
        g_adj[i*NS + j] = ep;    // symmetric/duplicate writes identical bits: race-free
        g_adj[j*NS + i] = ep;
    }
}

// ---------------- K6: per-row sparse nz lists (column-ascending, deterministic) ----------------
__global__ void __launch_bounds__(256) k_nzlist(){
    int wid  = (blockIdx.x*blockDim.x + threadIdx.x) >> 5;
    int lane = threadIdx.x & 31;
    if (wid >= NS) return;
    int cnt = 0;
    for (int base = 0; base < NS; base += 32){
        float v = g_adj[wid*NS + base + lane];
        unsigned m = __ballot_sync(0xffffffffu, v != 0.f);
        if (v != 0.f){
            int pos = cnt + __popc(m & ((1u << lane) - 1u));
            if (pos < MAXDEG){ g_nzc[wid*MAXDEG + pos] = base + lane; g_nzv[wid*MAXDEG + pos] = v; }
        }
        cnt += __popc(m);
    }
    int deg = min(cnt, MAXDEG);
    if (lane == 0){
        g_deg[wid] = deg;
        // ||row||^2: ascending-column sequential (zeros contribute exact 0 in any order)
        float s = 0.f;
        for (int t = 0; t < deg; t++){
            float v = g_nzv[wid*MAXDEG + t];
            s = __fadd_rn(s, __fmul_rn(v, v));
        }
        g_sqadj[wid] = s;
    }
}

// ---------------- K7: sparse adj@adjT row (== dense ascending-k), fd2, exact 16-NN ----------------
__global__ void __launch_bounds__(256) k_fd2knn(){
    __shared__ float sfd[NS];                    // 16 KB accumulate/dist buffer
    __shared__ int   sic[MAXDEG];
    __shared__ float siv[MAXDEG];
    __shared__ unsigned long long swin[8];
    const float INF = __int_as_float(0x7f800000);
    int i = blockIdx.x, t = threadIdx.x;         // 256 threads
    int lane = t & 31, warp = t >> 5;
    for (int k = t; k < NS; k += 256) sfd[k] = 0.f;
    int degi = g_deg[i];
    if (t < degi){ sic[t] = g_nzc[i*MAXDEG + t]; siv[t] = g_nzv[i*MAXDEG + t]; }
    __syncthreads();
    for (int jj = 0; jj < degi; jj++){           // ascending-j == dense ascending-k bitwise
        int   jcol = sic[jj];
        float aij  = siv[jj];
        if (t < g_deg[jcol]){
            int k = g_nzc[jcol*MAXDEG + t];      // distinct k within one j: no races
            sfd[k] = __fmaf_rn(aij, g_nzv[jcol*MAXDEG + t], sfd[k]);
        }
        __syncthreads();
    }
    float sqi = g_sqadj[i];
    for (int k = t; k < NS; k += 256){
        float fd = (k == i) ? INF : __fsub_rn(__fadd_rn(sqi, g_sqadj[k]), __fmul_rn(2.f, sfd[k]));
        sfd[k] = fd;
    }
    __syncthreads();
    for (int r = 0; r < KK; r++){
        unsigned long long best = 0xFFFFFFFFFFFFFFFFULL;
        for (int k = t; k < NS; k += 256){
            unsigned long long key = ((unsigned long long)ord_f(sfd[k]) << 32) | (unsigned)k;
            best = min(best, key);
        }
        #pragma unroll
        for (int o = 16; o > 0; o >>= 1)
            best = min(best, __shfl_down_sync(0xffffffffu, best, o));
        if (lane == 0) swin[warp] = best;
        __syncthreads();
        if (t == 0){
            unsigned long long b = swin[0];
            #pragma unroll
            for (int w = 1; w < 8; w++) b = min(b, swin[w]);
            int widx = (int)(b & 0xFFFFFFFFu);
            g_knn[i*KK + r] = widx;
            sfd[widx] = INF;
        }
        __syncthreads();
    }
}

// ---------------- K8: triangles, warp per pair (XLA matvec reduce for hf@wf2) ----------------
__global__ void __launch_bounds__(256) k_tri(const float* __restrict__ bf1,
                      const float* __restrict__ wf2,
                      float* __restrict__ out){
    __shared__ int   sk[KK];
    __shared__ float sAi[KK];
    __shared__ float sGi[HH];
    __shared__ float sGn[KK][HH+4];              // padded to dodge bank conflicts
    __shared__ float sb[HH], sw[HH];
    int i = blockIdx.x, t = threadIdx.x;         // 256 threads, 8 warps
    int lane = t & 31, warp = t >> 5;
    if (t < KK) sk[t] = g_knn[i*KK + t];
    if (t < HH){ sGi[t] = g_G[i*HH + t]; sb[t] = bf1[t]; sw[t] = wf2[t]; }
    __syncthreads();
    if (t < KK) sAi[t] = g_adj[i*NS + sk[t]];
    for (int q = warp; q < KK; q += 8){
        sGn[q][lane]      = g_G[sk[q]*HH + lane];
        sGn[q][lane+32]   = g_G[sk[q]*HH + lane + 32];
        sGn[q][lane+64]   = g_G[sk[q]*HH + lane + 64];
        sGn[q][lane+96]   = g_G[sk[q]*HH + lane + 96];
    }
    __syncthreads();
    const float third = 1.0f/3.0f;
    #pragma unroll
    for (int it = 0; it < NPAIR/8; it++){        // 15 iterations x 8 warps = 120 pairs
        int p0 = it*8 + warp;
        int p = p0, j = 0;
        while (p >= (KK - 1 - j)){ p -= (KK - 1 - j); j++; }   // triu_indices(16,1) order
        int l = j + 1 + p;
        // hf@wf2: lane partials k=lane+32m (rounded products, sequential adds), butterfly
        float s = 0.f;
        #pragma unroll
        for (int m = 0; m < 4; m++){
            int k = lane + 32*m;
            float pre = (sGi[k] + sGn[j][k] + sGn[l][k]) * third + sb[k];  // value-only path
            float hf  = fmaxf(pre, 0.f);
            s = __fadd_rn(s, __fmul_rn(hf, sw[k]));
        }
        s = warp_red_xla(s);
        if (lane == 0){
            int n1 = sk[j], n2 = sk[l];
            float a12  = g_adj[n1*NS + n2];
            bool valid = a12 > 0.f;
            float prod = __fmul_rn(__fmul_rn(sAi[j], sAi[l]), a12);
            float tpr  = valid ? cbrtf(fmaxf(prod, 1e-9f)) : 0.f;
            float fpr  = valid ? sigmoid_xla(s) : 0.f;
            out[i*NPAIR + p0]        = fpr;
            out[OUTM + i*NPAIR + p0] = tpr;
        }
    }
}

// ---------------- launch ----------------
extern "C" void kernel_launch(void* const* d_in, const int* in_sizes, int n_in,
                              void* d_out, int out_size){
    (void)in_sizes; (void)n_in; (void)out_size;
    const float* x   = (const float*)d_in[0];
    const float* pos = (const float*)d_in[1];
    const float* W1  = (const float*)d_in[2];
    const float* b1  = (const float*)d_in[3];
    const float* w2  = (const float*)d_in[4];
    const float* we  = (const float*)d_in[5];
    const float* Wf1 = (const float*)d_in[6];
    const float* bf1 = (const float*)d_in[7];
    const float* wf2 = (const float*)d_in[8];
    float* out = (float*)d_out;

    k_zero_adj<<<1184, 256>>>();                 // 148 SMs x 8 blocks, fixed grid
    k_probs<<<NN/4, 128>>>(x, W1, b1, w2);       // 2000 blocks, exact cover
    k_rank<<<(NN + 255)/256, 256>>>();
    k_gather<<<NS, HH>>>(x, pos, Wf1);
    k_knn_pos<<<(NS + 127)/128, 128>>>();
    k_edges<<<(NS*EK + 7)/8, 256>>>(we);
    k_nzlist<<<NS/8, 256>>>();
    k_fd2knn<<<NS, 256>>>();
    k_tri<<<NS, 256>>>(bf1, wf2, out);
}

// round 11
// speedup vs baseline: 1.5426x; 1.5426x over previous
#include <cuda_runtime.h>
#include <math.h>
#include <stdint.h>

#define NN 8000
#define NS 4000
#define DD 64
#define HH 128
#define EK 15
#define KK 16
#define MAXDEG 256
#define NPAIR 120
#define OUTM (NS*NPAIR)

// ---------------- device scratch (static, no dynamic allocation) ----------------
__device__ __align__(16) float g_adj[NS*NS];          // 64 MB dense symmetric adjacency
__device__ unsigned long long g_key[NN];
__device__ int   g_cnt[NN];
__device__ int   g_sel[NS];
__device__ __align__(16) float g_sx[NS*DD];
__device__ __align__(16) float g_sp[NS*4];            // x,y,z,sq
__device__ float g_G[NS*HH];
__device__ int   g_nbr[NS*EK];
__device__ int   g_deg[NS];
__device__ __align__(16) int   g_nzc[NS*MAXDEG];
__device__ __align__(16) float g_nzv[NS*MAXDEG];
__device__ float g_sqadj[NS];
__device__ int   g_knn[NS*KK];

__device__ __forceinline__ unsigned ord_f(float f){
    unsigned u = __float_as_uint(f);
    return (u & 0x80000000u) ? ~u : (u | 0x80000000u);   // ascending-float -> ascending-uint
}
__device__ __forceinline__ unsigned long long umin64(unsigned long long a, unsigned long long b){
    return a < b ? a : b;
}

// ---- XLA/Eigen fast tanh (f32), bit-exact replication ----
__device__ __forceinline__ float tanh_xla(float x){
    float ax = fabsf(x);
    if (ax < 0.0004f) return x;                           // XLA kCanUseApprox shortcut
    float xc = fminf(fmaxf(x, -7.90531110763549805f), 7.90531110763549805f);
    float x2 = __fmul_rn(xc, xc);
    float p = __fmaf_rn(x2, -2.76076847742355e-16f, 2.00018790482477e-13f);
    p = __fmaf_rn(x2, p, -8.60467152213735e-11f);
    p = __fmaf_rn(x2, p,  5.12229709037114e-08f);
    p = __fmaf_rn(x2, p,  1.48572235717979e-05f);
    p = __fmaf_rn(x2, p,  6.37261928875436e-04f);
    p = __fmaf_rn(x2, p,  4.89352455891786e-03f);
    p = __fmul_rn(p, xc);
    float q = __fmaf_rn(x2, 1.19825839466702e-06f, 1.18534705686654e-04f);
    q = __fmaf_rn(x2, q, 2.26843463243900e-03f);
    q = __fmaf_rn(x2, q, 4.89352518554385e-03f);
    return __fdiv_rn(p, q);
}
// XLA logistic expansion: 0.5 + 0.5 * tanh(0.5 * x)
__device__ __forceinline__ float sigmoid_xla(float v){
    return __fadd_rn(0.5f, __fmul_rn(0.5f, tanh_xla(__fmul_rn(0.5f, v))));
}
// XLA row-reduction warp tail: shfl_down butterfly 16..1, result in lane 0
__device__ __forceinline__ float warp_red_xla(float s){
    #pragma unroll
    for (int o = 16; o > 0; o >>= 1)
        s = __fadd_rn(s, __shfl_down_sync(0xffffffffu, s, o));
    return s;
}

// ---------------- K0: zero adjacency + rank counters ----------------
__global__ void __launch_bounds__(256) k_zero_adj(){
    float4 z = make_float4(0.f,0.f,0.f,0.f);
    float4* p = reinterpret_cast<float4*>(g_adj);
    const int n4 = (NS*NS)/4;
    for (int i = blockIdx.x*blockDim.x + threadIdx.x; i < n4; i += gridDim.x*blockDim.x)
        p[i] = z;
    for (int i = blockIdx.x*blockDim.x + threadIdx.x; i < NN; i += gridDim.x*blockDim.x)
        g_cnt[i] = 0;
}

// ---------------- K1: probs = sigmoid_xla(relu(x@W1+b1)@w2), warp per node ----------------
// W1 staged in shared (identical values -> identical bits). Math unchanged from passing R10.
__global__ void __launch_bounds__(128) k_probs(const float* __restrict__ x,
                        const float* __restrict__ W1,
                        const float* __restrict__ b1, const float* __restrict__ w2){
    __shared__ float xs[4][DD];
    __shared__ float sW1[DD*HH];                // 32 KB
    int warp = threadIdx.x >> 5, lane = threadIdx.x & 31;
    const float4* wsrc = reinterpret_cast<const float4*>(W1);
    float4* wdst = reinterpret_cast<float4*>(sW1);
    #pragma unroll
    for (int u = 0; u < (DD*HH/4)/128; u++)
        wdst[threadIdx.x + 128*u] = wsrc[threadIdx.x + 128*u];
    int n = blockIdx.x*4 + warp;                // 8000 nodes, 4 warps/block, grid=2000
    xs[warp][lane]      = x[n*DD + lane];
    xs[warp][lane + 32] = x[n*DD + lane + 32];
    __syncthreads();
    float s = 0.f;
    #pragma unroll
    for (int j = 0; j < 4; j++){
        int k = lane + 32*j;
        float h = 0.f;
        #pragma unroll
        for (int d = 0; d < DD; d++) h = __fmaf_rn(xs[warp][d], sW1[d*HH + k], h);
        h = fmaxf(__fadd_rn(h, b1[k]), 0.f);
        float m = __fmul_rn(h, w2[k]);
        s = __fadd_rn(s, m);                    // sequential ascending-j adds
    }
    s = warp_red_xla(s);
    if (lane == 0){
        float p = sigmoid_xla(s);
        g_key[n] = ((unsigned long long)ord_f(p) << 32) | (unsigned)(NN - 1 - n); // tie->lower n
    }
}

// ---------------- K2a: partial exact ranking (quarter scans, int-atomic merge) ----------------
__global__ void __launch_bounds__(256) k_rank_a(){
    __shared__ unsigned long long sk[256];
    int qt = blockIdx.x >> 5;                   // quarter 0..3
    int nb = blockIdx.x & 31;                   // node block 0..31
    int n = nb*256 + threadIdx.x;               // 0..8191
    unsigned long long my = (n < NN) ? g_key[n] : 0ULL;
    int cnt = 0;
    int lo = qt*(NN/4), hi = lo + NN/4;         // 2000-wide key range
    for (int base = lo; base < hi; base += 256){
        int idx = base + threadIdx.x;
        sk[threadIdx.x] = (idx < hi) ? g_key[idx] : 0ULL;
        __syncthreads();
        int lim = min(256, hi - base);
        for (int k = 0; k < lim; k++) cnt += (sk[k] > my) ? 1 : 0;
        __syncthreads();
    }
    if (n < NN && cnt > 0) atomicAdd(&g_cnt[n], cnt);   // int add: order-independent exact
}
// ---------------- K2b: scatter selected order ----------------
__global__ void __launch_bounds__(256) k_rank_b(){
    int n = blockIdx.x*256 + threadIdx.x;
    if (n < NN){
        int c = g_cnt[n];
        if (c < NS) g_sel[c] = n;
    }
}

// ---------------- K3: gather sx/sp, pos norms, G = [sx,sp] @ Wf1 (value-only path) ----------------
__global__ void __launch_bounds__(HH) k_gather(const float* __restrict__ x,
                         const float* __restrict__ pos,
                         const float* __restrict__ Wf1){
    __shared__ float xs[DD];
    __shared__ float ps[3];
    __shared__ float sW[(DD+3)*HH];             // 34.3 KB
    int r = blockIdx.x, t = threadIdx.x;        // 128 threads
    for (int u = t; u < (DD+3)*HH; u += HH) sW[u] = Wf1[u];
    int i = g_sel[r];
    if (t < DD){ float v = x[i*DD + t]; xs[t] = v; g_sx[r*DD + t] = v; }
    if (t < 3){ float v = pos[i*3 + t]; ps[t] = v; g_sp[r*4 + t] = v; }
    __syncthreads();
    if (t == 0){
        // sq = (x^2 + y^2) + z^2, squares rounded separately (square-then-reduce, NO fma)
        float sq = __fadd_rn(__fadd_rn(__fmul_rn(ps[0],ps[0]), __fmul_rn(ps[1],ps[1])),
                             __fmul_rn(ps[2],ps[2]));
        g_sp[r*4 + 3] = sq;
    }
    float g = 0.f;
    #pragma unroll
    for (int d = 0; d < DD; d++) g = fmaf(xs[d], sW[d*HH + t], g);
    #pragma unroll
    for (int c = 0; c < 3; c++)  g = fmaf(ps[c], sW[(DD + c)*HH + t], g);
    g_G[r*HH + t] = g;
}

// ---------------- K4: 15-NN over positions, 4 threads/row + exact lex merge ----------------
// Same d2 bits as R10-pass. Selection: per-thread (d2,idx)-lex top-15 over its quarter
// (position-count insertion: no dependent bubble chain), then 4-way merge of lex-sorted
// lists == global top_k with ties->lower idx.
__global__ void __launch_bounds__(128) k_knn_pos(){
    __shared__ float4 tile[128];
    __shared__ unsigned long long lists[128*EK]; // 15 KB
    int tid = threadIdx.x;
    int gid = blockIdx.x*128 + tid;              // 16000 = 4000 rows x 4
    int row = gid >> 2, q = gid & 3;
    float4 m = *reinterpret_cast<const float4*>(&g_sp[row*4]);
    float px = m.x, py = m.y, pz = m.z, sqi = m.w;
    const int QW = NS/4;                         // 1000
    int qlo = q*QW, qhi = qlo + QW;
    float bd[EK]; int bi[EK];
    #pragma unroll
    for (int s = 0; s < EK; s++){ bd[s] = 3.4e38f; bi[s] = 0; }
    for (int base = 0; base < NS; base += 128){
        int c = base + tid;
        if (c < NS) tile[tid] = *reinterpret_cast<const float4*>(&g_sp[c*4]);
        __syncthreads();
        int lo = max(base, qlo), hi = min(base + 128, qhi);
        for (int c2 = lo; c2 < hi; c2++){
            if (c2 == row) continue;
            float4 qv = tile[c2 - base];
            // acc=0; fma k=0,1,2  ->  fma(z, q.z, fma(y, q.y, round(x*q.x)))  [R10-pass bits]
            float dot = __fmaf_rn(pz, qv.z, __fmaf_rn(py, qv.y, __fmul_rn(px, qv.x)));
            float d2  = __fsub_rn(__fadd_rn(sqi, qv.w), __fmul_rn(2.f, dot));
            if (d2 < bd[EK-1]){
                int pos = 0;
                #pragma unroll
                for (int s = 0; s < EK; s++) pos += (bd[s] <= d2) ? 1 : 0;  // ties -> after
                #pragma unroll
                for (int s = EK-1; s > 0; s--){
                    if (s > pos){ bd[s] = bd[s-1]; bi[s] = bi[s-1]; }
                }
                #pragma unroll
                for (int s = 0; s < EK; s++){
                    if (s == pos){ bd[s] = d2; bi[s] = c2; }
                }
            }
        }
        __syncthreads();
    }
    #pragma unroll
    for (int s = 0; s < EK; s++)
        lists[tid*EK + s] = ((unsigned long long)ord_f(bd[s]) << 32) | (unsigned)bi[s];
    __syncthreads();
    if (q == 0){
        int h0 = 0, h1 = 0, h2 = 0, h3 = 0;
        #pragma unroll
        for (int r = 0; r < EK; r++){
            unsigned long long v0 = (h0 < EK) ? lists[(tid+0)*EK + h0] : ~0ULL;
            unsigned long long v1 = (h1 < EK) ? lists[(tid+1)*EK + h1] : ~0ULL;
            unsigned long long v2 = (h2 < EK) ? lists[(tid+2)*EK + h2] : ~0ULL;
            unsigned long long v3 = (h3 < EK) ? lists[(tid+3)*EK + h3] : ~0ULL;
            unsigned long long best = umin64(umin64(v0, v1), umin64(v2, v3));
            if (best == v0) h0++; else if (best == v1) h1++; else if (best == v2) h2++; else h3++;
            g_nbr[row*EK + r] = (int)(best & 0xFFFFFFFFu);
        }
    }
}

// ---------------- K5: edge probs, warp per edge (XLA mult+row-reduce shape) ----------------
__global__ void __launch_bounds__(256) k_edges(const float* __restrict__ we){
    int e = blockIdx.x*8 + (threadIdx.x >> 5);
    int lane = threadIdx.x & 31;
    if (e >= NS*EK) return;
    int i = e / EK;
    int j = g_nbr[e];
    const float* a = &g_sx[i*DD];
    const float* b = &g_sx[j*DD];
    // z_k = round(a_k*b_k); m_k = round(z_k*w_k); lane partial = m_lane + m_{lane+32}
    float m0 = __fmul_rn(__fmul_rn(a[lane],      b[lane]),      we[lane]);
    float m1 = __fmul_rn(__fmul_rn(a[lane + 32], b[lane + 32]), we[lane + 32]);
    float s  = __fadd_rn(m0, m1);
    s = warp_red_xla(s);
    if (lane == 0){
        float ep = sigmoid_xla(s);
        g_adj[i*NS + j] = ep;    // symmetric/duplicate writes identical bits: race-free
        g_adj[j*NS + i] = ep;
    }
}

// ---------------- K6: per-row sparse nz lists (column-ascending, deterministic) ----------------
__global__ void __launch_bounds__(256) k_nzlist(){
    int wid  = (blockIdx.x*blockDim.x + threadIdx.x) >> 5;
    int lane = threadIdx.x & 31;
    if (wid >= NS) return;
    int cnt = 0;
    for (int base = 0; base < NS; base += 32){
        float v = g_adj[wid*NS + base + lane];
        unsigned m = __ballot_sync(0xffffffffu, v != 0.f);
        if (v != 0.f){
            int pos = cnt + __popc(m & ((1u << lane) - 1u));
            if (pos < MAXDEG){ g_nzc[wid*MAXDEG + pos] = base + lane; g_nzv[wid*MAXDEG + pos] = v; }
        }
        cnt += __popc(m);
    }
    int deg = min(cnt, MAXDEG);
    if (lane == 0){
        g_deg[wid] = deg;
        // ||row||^2: ascending-column sequential (zeros contribute exact 0 in any order)
        float s = 0.f;
        for (int t = 0; t < deg; t++){
            float v = g_nzv[wid*MAXDEG + t];
            s = __fadd_rn(s, __fmul_rn(v, v));
        }
        g_sqadj[wid] = s;
    }
}

// ---------------- K7: sparse adj@adjT row (== dense ascending-k), fd2, exact 16-NN ----------------
// Selection via register-cached u64 keys: one block-min per round, only the winner rebuilds.
__global__ void __launch_bounds__(256) k_fd2knn(){
    __shared__ float sfd[NS];                    // 16 KB accumulate buffer
    __shared__ int   sic[MAXDEG];
    __shared__ float siv[MAXDEG];
    __shared__ unsigned long long swin[8];
    __shared__ unsigned long long sbest;
    int i = blockIdx.x, t = threadIdx.x;         // 256 threads
    int lane = t & 31, warp = t >> 5;
    for (int k = t; k < NS; k += 256) sfd[k] = 0.f;
    int degi = g_deg[i];
    if (t < degi){ sic[t] = g_nzc[i*MAXDEG + t]; siv[t] = g_nzv[i*MAXDEG + t]; }
    __syncthreads();
    for (int jj = 0; jj < degi; jj++){           // ascending-j == dense ascending-k bitwise
        int   jcol = sic[jj];
        float aij  = siv[jj];
        if (t < g_deg[jcol]){
            int k = g_nzc[jcol*MAXDEG + t];      // distinct k within one j: no races
            sfd[k] = __fmaf_rn(aij, g_nzv[jcol*MAXDEG + t], sfd[k]);
        }
        __syncthreads();
    }
    float sqi = g_sqadj[i];
    unsigned long long lk[16];
    #pragma unroll
    for (int m = 0; m < 16; m++){
        int k = t + 256*m;
        unsigned long long key = ~0ULL;
        if (k < NS && k != i){
            float fd = __fsub_rn(__fadd_rn(sqi, g_sqadj[k]), __fmul_rn(2.f, sfd[k]));
            key = ((unsigned long long)ord_f(fd) << 32) | (unsigned)k;
        }
        lk[m] = key;
    }
    unsigned long long lmin = lk[0];
    #pragma unroll
    for (int m = 1; m < 16; m++) lmin = umin64(lmin, lk[m]);
    for (int r = 0; r < KK; r++){
        unsigned long long b = lmin;
        #pragma unroll
        for (int o = 16; o > 0; o >>= 1) b = umin64(b, __shfl_down_sync(0xffffffffu, b, o));
        if (lane == 0) swin[warp] = b;
        __syncthreads();
        if (t == 0){
            unsigned long long bb = swin[0];
            #pragma unroll
            for (int w = 1; w < 8; w++) bb = umin64(bb, swin[w]);
            sbest = bb;
            g_knn[i*KK + r] = (int)(bb & 0xFFFFFFFFu);
        }
        __syncthreads();
        unsigned long long best = sbest;
        if (lmin == best){                       // unique key (idx embedded): one owner
            #pragma unroll
            for (int m = 0; m < 16; m++) if (lk[m] == best) lk[m] = ~0ULL;
            lmin = lk[0];
            #pragma unroll
            for (int m = 1; m < 16; m++) lmin = umin64(lmin, lk[m]);
        }
        __syncthreads();
    }
}

// ---------------- K8: triangles, warp per pair (XLA matvec reduce for hf@wf2) ----------------
__global__ void __launch_bounds__(256) k_tri(const float* __restrict__ bf1,
                      const float* __restrict__ wf2,
                      float* __restrict__ out){
    __shared__ int   sk[KK];
    __shared__ float sAi[KK];
    __shared__ float sGi[HH];
    __shared__ float sGn[KK][HH+4];              // padded to dodge bank conflicts
    __shared__ float sb[HH], sw[HH];
    int i = blockIdx.x, t = threadIdx.x;         // 256 threads, 8 warps
    int lane = t & 31, warp = t >> 5;
    if (t < KK) sk[t] = g_knn[i*KK + t];
    if (t < HH){ sGi[t] = g_G[i*HH + t]; sb[t] = bf1[t]; sw[t] = wf2[t]; }
    __syncthreads();
    if (t < KK) sAi[t] = g_adj[i*NS + sk[t]];
    for (int q = warp; q < KK; q += 8){
        sGn[q][lane]      = g_G[sk[q]*HH + lane];
        sGn[q][lane+32]   = g_G[sk[q]*HH + lane + 32];
        sGn[q][lane+64]   = g_G[sk[q]*HH + lane + 64];
        sGn[q][lane+96]   = g_G[sk[q]*HH + lane + 96];
    }
    __syncthreads();
    const float third = 1.0f/3.0f;
    #pragma unroll
    for (int it = 0; it < NPAIR/8; it++){        // 15 iterations x 8 warps = 120 pairs
        int p0 = it*8 + warp;
        int p = p0, j = 0;
        while (p >= (KK - 1 - j)){ p -= (KK - 1 - j); j++; }   // triu_indices(16,1) order
        int l = j + 1 + p;
        // hf@wf2: lane partials k=lane+32m (rounded products, sequential adds), butterfly
        float s = 0.f;
        #pragma unroll
        for (int m = 0; m < 4; m++){
            int k = lane + 32*m;
            float pre = (sGi[k] + sGn[j][k] + sGn[l][k]) * third + sb[k];  // value-only path
            float hf  = fmaxf(pre, 0.f);
            s = __fadd_rn(s, __fmul_rn(hf, sw[k]));
        }
        s = warp_red_xla(s);
        if (lane == 0){
            int n1 = sk[j], n2 = sk[l];
            float a12  = g_adj[n1*NS + n2];
            bool valid = a12 > 0.f;
            float prod = __fmul_rn(__fmul_rn(sAi[j], sAi[l]), a12);
            float tpr  = valid ? cbrtf(fmaxf(prod, 1e-9f)) : 0.f;
            float fpr  = valid ? sigmoid_xla(s) : 0.f;
            out[i*NPAIR + p0]        = fpr;
            out[OUTM + i*NPAIR + p0] = tpr;
        }
    }
}

// ---------------- launch ----------------
extern "C" void kernel_launch(void* const* d_in, const int* in_sizes, int n_in,
                              void* d_out, int out_size){
    (void)in_sizes; (void)n_in; (void)out_size;
    const float* x   = (const float*)d_in[0];
    const float* pos = (const float*)d_in[1];
    const float* W1  = (const float*)d_in[2];
    const float* b1  = (const float*)d_in[3];
    const float* w2  = (const float*)d_in[4];
    const float* we  = (const float*)d_in[5];
    const float* Wf1 = (const float*)d_in[6];
    const float* bf1 = (const float*)d_in[7];
    const float* wf2 = (const float*)d_in[8];
    float* out = (float*)d_out;

    k_zero_adj<<<1184, 256>>>();                 // 148 SMs x 8 blocks
    k_probs<<<NN/4, 128>>>(x, W1, b1, w2);       // 2000 blocks
    k_rank_a<<<128, 256>>>();                    // 4 quarters x 32 node-blocks
    k_rank_b<<<32, 256>>>();
    k_gather<<<NS, HH>>>(x, pos, Wf1);
    k_knn_pos<<<125, 128>>>();                   // 4000 rows x 4 scanners
    k_edges<<<(NS*EK + 7)/8, 256>>>(we);
    k_nzlist<<<NS/8, 256>>>();
    k_fd2knn<<<NS, 256>>>();
    k_tri<<<NS, 256>>>(bf1, wf2, out);
}

// round 12
// speedup vs baseline: 1.5848x; 1.0274x over previous
#include <cuda_runtime.h>
#include <math.h>
#include <stdint.h>

#define NN 8000
#define NS 4000
#define DD 64
#define HH 128
#define EK 15
#define KK 16
#define MAXDEG 256
#define NPAIR 120
#define OUTM (NS*NPAIR)

// ---------------- device scratch (static, no dynamic allocation) ----------------
__device__ __align__(16) float g_adj[NS*NS];          // 64 MB dense symmetric adjacency
__device__ unsigned long long g_key[NN];
__device__ int   g_cnt[NN];
__device__ int   g_sel[NS];
__device__ __align__(16) float g_sx[NS*DD];
__device__ __align__(16) float g_sp[NS*4];            // x,y,z,sq
__device__ float g_G[NS*HH];
__device__ int   g_nbr[NS*EK];
__device__ int   g_deg[NS];
__device__ __align__(16) int   g_nzc[NS*MAXDEG];
__device__ __align__(16) float g_nzv[NS*MAXDEG];
__device__ float g_sqadj[NS];
__device__ int   g_knn[NS*KK];

__device__ __forceinline__ unsigned ord_f(float f){
    unsigned u = __float_as_uint(f);
    return (u & 0x80000000u) ? ~u : (u | 0x80000000u);   // ascending-float -> ascending-uint
}
__device__ __forceinline__ unsigned long long umin64(unsigned long long a, unsigned long long b){
    return a < b ? a : b;
}

// ---- XLA/Eigen fast tanh (f32), bit-exact replication ----
__device__ __forceinline__ float tanh_xla(float x){
    float ax = fabsf(x);
    if (ax < 0.0004f) return x;                           // XLA kCanUseApprox shortcut
    float xc = fminf(fmaxf(x, -7.90531110763549805f), 7.90531110763549805f);
    float x2 = __fmul_rn(xc, xc);
    float p = __fmaf_rn(x2, -2.76076847742355e-16f, 2.00018790482477e-13f);
    p = __fmaf_rn(x2, p, -8.60467152213735e-11f);
    p = __fmaf_rn(x2, p,  5.12229709037114e-08f);
    p = __fmaf_rn(x2, p,  1.48572235717979e-05f);
    p = __fmaf_rn(x2, p,  6.37261928875436e-04f);
    p = __fmaf_rn(x2, p,  4.89352455891786e-03f);
    p = __fmul_rn(p, xc);
    float q = __fmaf_rn(x2, 1.19825839466702e-06f, 1.18534705686654e-04f);
    q = __fmaf_rn(x2, q, 2.26843463243900e-03f);
    q = __fmaf_rn(x2, q, 4.89352518554385e-03f);
    return __fdiv_rn(p, q);
}
// XLA logistic expansion: 0.5 + 0.5 * tanh(0.5 * x)
__device__ __forceinline__ float sigmoid_xla(float v){
    return __fadd_rn(0.5f, __fmul_rn(0.5f, tanh_xla(__fmul_rn(0.5f, v))));
}
// XLA row-reduction warp tail: shfl_down butterfly 16..1, result in lane 0
__device__ __forceinline__ float warp_red_xla(float s){
    #pragma unroll
    for (int o = 16; o > 0; o >>= 1)
        s = __fadd_rn(s, __shfl_down_sync(0xffffffffu, s, o));
    return s;
}

// ---------------- K0: zero adjacency + rank counters ----------------
__global__ void __launch_bounds__(256) k_zero_adj(){
    float4 z = make_float4(0.f,0.f,0.f,0.f);
    float4* p = reinterpret_cast<float4*>(g_adj);
    const int n4 = (NS*NS)/4;
    for (int i = blockIdx.x*blockDim.x + threadIdx.x; i < n4; i += gridDim.x*blockDim.x)
        p[i] = z;
    for (int i = blockIdx.x*blockDim.x + threadIdx.x; i < NN; i += gridDim.x*blockDim.x)
        g_cnt[i] = 0;
}

// ---------------- K1: probs = sigmoid_xla(relu(x@W1+b1)@w2), warp per node ----------------
__global__ void __launch_bounds__(128) k_probs(const float* __restrict__ x,
                        const float* __restrict__ W1,
                        const float* __restrict__ b1, const float* __restrict__ w2){
    __shared__ float xs[4][DD];
    __shared__ float sW1[DD*HH];                // 32 KB
    int warp = threadIdx.x >> 5, lane = threadIdx.x & 31;
    const float4* wsrc = reinterpret_cast<const float4*>(W1);
    float4* wdst = reinterpret_cast<float4*>(sW1);
    #pragma unroll
    for (int u = 0; u < (DD*HH/4)/128; u++)
        wdst[threadIdx.x + 128*u] = wsrc[threadIdx.x + 128*u];
    int n = blockIdx.x*4 + warp;                // 8000 nodes, 4 warps/block, grid=2000
    xs[warp][lane]      = x[n*DD + lane];
    xs[warp][lane + 32] = x[n*DD + lane + 32];
    __syncthreads();
    float s = 0.f;
    #pragma unroll
    for (int j = 0; j < 4; j++){
        int k = lane + 32*j;
        float h = 0.f;
        #pragma unroll
        for (int d = 0; d < DD; d++) h = __fmaf_rn(xs[warp][d], sW1[d*HH + k], h);
        h = fmaxf(__fadd_rn(h, b1[k]), 0.f);
        float m = __fmul_rn(h, w2[k]);
        s = __fadd_rn(s, m);                    // sequential ascending-j adds
    }
    s = warp_red_xla(s);
    if (lane == 0){
        float p = sigmoid_xla(s);
        g_key[n] = ((unsigned long long)ord_f(p) << 32) | (unsigned)(NN - 1 - n); // tie->lower n
    }
}

// ---------------- K2a: partial exact ranking (quarter scans, int-atomic merge) ----------------
__global__ void __launch_bounds__(256) k_rank_a(){
    __shared__ unsigned long long sk[256];
    int qt = blockIdx.x >> 5;                   // quarter 0..3
    int nb = blockIdx.x & 31;                   // node block 0..31
    int n = nb*256 + threadIdx.x;               // 0..8191
    unsigned long long my = (n < NN) ? g_key[n] : 0ULL;
    int cnt = 0;
    int lo = qt*(NN/4), hi = lo + NN/4;         // 2000-wide key range
    for (int base = lo; base < hi; base += 256){
        int idx = base + threadIdx.x;
        sk[threadIdx.x] = (idx < hi) ? g_key[idx] : 0ULL;
        __syncthreads();
        int lim = min(256, hi - base);
        for (int k = 0; k < lim; k++) cnt += (sk[k] > my) ? 1 : 0;
        __syncthreads();
    }
    if (n < NN && cnt > 0) atomicAdd(&g_cnt[n], cnt);   // int add: order-independent exact
}
// ---------------- K2b: scatter selected order ----------------
__global__ void __launch_bounds__(256) k_rank_b(){
    int n = blockIdx.x*256 + threadIdx.x;
    if (n < NN){
        int c = g_cnt[n];
        if (c < NS) g_sel[c] = n;
    }
}

// ---------------- K3: gather sx/sp, pos norms, G = [sx,sp] @ Wf1 (value-only path) ----------------
__global__ void __launch_bounds__(HH) k_gather(const float* __restrict__ x,
                         const float* __restrict__ pos,
                         const float* __restrict__ Wf1){
    __shared__ float xs[DD];
    __shared__ float ps[3];
    __shared__ float sW[(DD+3)*HH];             // 34.3 KB
    int r = blockIdx.x, t = threadIdx.x;        // 128 threads
    for (int u = t; u < (DD+3)*HH; u += HH) sW[u] = Wf1[u];
    int i = g_sel[r];
    if (t < DD){ float v = x[i*DD + t]; xs[t] = v; g_sx[r*DD + t] = v; }
    if (t < 3){ float v = pos[i*3 + t]; ps[t] = v; g_sp[r*4 + t] = v; }
    __syncthreads();
    if (t == 0){
        // sq = (x^2 + y^2) + z^2, squares rounded separately (square-then-reduce, NO fma)
        float sq = __fadd_rn(__fadd_rn(__fmul_rn(ps[0],ps[0]), __fmul_rn(ps[1],ps[1])),
                             __fmul_rn(ps[2],ps[2]));
        g_sp[r*4 + 3] = sq;
    }
    float g = 0.f;
    #pragma unroll
    for (int d = 0; d < DD; d++) g = fmaf(xs[d], sW[d*HH + t], g);
    #pragma unroll
    for (int c = 0; c < 3; c++)  g = fmaf(ps[c], sW[(DD + c)*HH + t], g);
    g_G[r*HH + t] = g;
}

// ---------------- K4: 15-NN over positions — warp per quarter, lane per row ----------------
// Identical bits/order to R11-pass: same quarter partition, same ascending scan, same
// strict-< + position-count insertion (ties after), same lex 4-way merge. Only the
// thread mapping changed: all lanes of a warp share the scan range -> no divergence,
// tile reads are LDS broadcasts, warp-private staging needs no block barriers.
#define INSERT15(D2, CC) do{ \
    int pos = 0; \
    _Pragma("unroll") \
    for (int s = 0; s < EK; s++) pos += (bd[s] <= (D2)) ? 1 : 0; \
    _Pragma("unroll") \
    for (int s = EK-1; s > 0; s--){ if (s > pos){ bd[s] = bd[s-1]; bi[s] = bi[s-1]; } } \
    _Pragma("unroll") \
    for (int s = 0; s < EK; s++){ if (s == pos){ bd[s] = (D2); bi[s] = (CC); } } \
}while(0)

__global__ void __launch_bounds__(128) k_knn_pos(){
    __shared__ float4 tile[4][132];                       // per-warp staging
    __shared__ unsigned long long lists[4][32][EK];       // 15.4 KB
    int lane = threadIdx.x & 31, q = threadIdx.x >> 5;    // warp == quarter
    int row = blockIdx.x*32 + lane;                       // 125 blocks x 32 rows
    float4 m = *reinterpret_cast<const float4*>(&g_sp[row*4]);
    float px = m.x, py = m.y, pz = m.z, sqi = m.w;
    const int QW = NS/4;                                   // 1000
    const int qlo = q*QW;
    float bd[EK]; int bi[EK];
    #pragma unroll
    for (int s = 0; s < EK; s++){ bd[s] = 3.4e38f; bi[s] = 0; }
    for (int t0 = 0; t0 < QW; t0 += 128){
        int nload = min(128, QW - t0);                     // 128,...,128,104 (all even)
        for (int u = lane; u < nload; u += 32)
            tile[q][u] = *reinterpret_cast<const float4*>(&g_sp[(qlo + t0 + u)*4]);
        __syncwarp();
        for (int u = 0; u < nload; u += 2){
            int c0 = qlo + t0 + u, c1 = c0 + 1;
            float4 q0 = tile[q][u], q1 = tile[q][u+1];
            // acc=0; fma k=0,1,2 -> fma(z,qz, fma(y,qy, round(x*qx)))  [R10/R11-pass bits]
            float dot0 = __fmaf_rn(pz, q0.z, __fmaf_rn(py, q0.y, __fmul_rn(px, q0.x)));
            float dot1 = __fmaf_rn(pz, q1.z, __fmaf_rn(py, q1.y, __fmul_rn(px, q1.x)));
            float d20  = __fsub_rn(__fadd_rn(sqi, q0.w), __fmul_rn(2.f, dot0));
            float d21  = __fsub_rn(__fadd_rn(sqi, q1.w), __fmul_rn(2.f, dot1));
            if (c0 != row && d20 < bd[EK-1]) INSERT15(d20, c0);   // ascending order kept
            if (c1 != row && d21 < bd[EK-1]) INSERT15(d21, c1);
        }
        __syncwarp();
    }
    #pragma unroll
    for (int s = 0; s < EK; s++)
        lists[q][lane][s] = ((unsigned long long)ord_f(bd[s]) << 32) | (unsigned)bi[s];
    __syncthreads();
    if (threadIdx.x < 32){
        int r2 = blockIdx.x*32 + threadIdx.x;
        int h0 = 0, h1 = 0, h2 = 0, h3 = 0;
        #pragma unroll
        for (int r = 0; r < EK; r++){
            unsigned long long v0 = (h0 < EK) ? lists[0][threadIdx.x][h0] : ~0ULL;
            unsigned long long v1 = (h1 < EK) ? lists[1][threadIdx.x][h1] : ~0ULL;
            unsigned long long v2 = (h2 < EK) ? lists[2][threadIdx.x][h2] : ~0ULL;
            unsigned long long v3 = (h3 < EK) ? lists[3][threadIdx.x][h3] : ~0ULL;
            unsigned long long best = umin64(umin64(v0, v1), umin64(v2, v3));
            if (best == v0) h0++; else if (best == v1) h1++; else if (best == v2) h2++; else h3++;
            g_nbr[r2*EK + r] = (int)(best & 0xFFFFFFFFu);
        }
    }
}

// ---------------- K5: edge probs, warp per edge (XLA mult+row-reduce shape) ----------------
__global__ void __launch_bounds__(256) k_edges(const float* __restrict__ we){
    int e = blockIdx.x*8 + (threadIdx.x >> 5);
    int lane = threadIdx.x & 31;
    if (e >= NS*EK) return;
    int i = e / EK;
    int j = g_nbr[e];
    const float* a = &g_sx[i*DD];
    const float* b = &g_sx[j*DD];
    // z_k = round(a_k*b_k); m_k = round(z_k*w_k); lane partial = m_lane + m_{lane+32}
    float m0 = __fmul_rn(__fmul_rn(a[lane],      b[lane]),      we[lane]);
    float m1 = __fmul_rn(__fmul_rn(a[lane + 32], b[lane + 32]), we[lane + 32]);
    float s  = __fadd_rn(m0, m1);
    s = warp_red_xla(s);
    if (lane == 0){
        float ep = sigmoid_xla(s);
        g_adj[i*NS + j] = ep;    // symmetric/duplicate writes identical bits: race-free
        g_adj[j*NS + i] = ep;
    }
}

// ---------------- K6: per-row sparse nz lists (column-ascending, deterministic) ----------------
__global__ void __launch_bounds__(256) k_nzlist(){
    int wid  = (blockIdx.x*blockDim.x + threadIdx.x) >> 5;
    int lane = threadIdx.x & 31;
    if (wid >= NS) return;
    int cnt = 0;
    for (int base = 0; base < NS; base += 32){
        float v = g_adj[wid*NS + base + lane];
        unsigned m = __ballot_sync(0xffffffffu, v != 0.f);
        if (v != 0.f){
            int pos = cnt + __popc(m & ((1u << lane) - 1u));
            if (pos < MAXDEG){ g_nzc[wid*MAXDEG + pos] = base + lane; g_nzv[wid*MAXDEG + pos] = v; }
        }
        cnt += __popc(m);
    }
    int deg = min(cnt, MAXDEG);
    if (lane == 0){
        g_deg[wid] = deg;
        // ||row||^2: ascending-column sequential (zeros contribute exact 0 in any order)
        float s = 0.f;
        for (int t = 0; t < deg; t++){
            float v = g_nzv[wid*MAXDEG + t];
            s = __fadd_rn(s, __fmul_rn(v, v));
        }
        g_sqadj[wid] = s;
    }
}

// ---------------- K7: sparse adj@adjT row, fd2, exact 16-NN (prefetch pipeline) ----------------
__global__ void __launch_bounds__(256) k_fd2knn(){
    __shared__ float sfd[NS];                    // 16 KB accumulate buffer
    __shared__ int   sic[MAXDEG];
    __shared__ float siv[MAXDEG];
    __shared__ int   sdeg[MAXDEG];
    __shared__ unsigned long long swin[8];
    __shared__ unsigned long long sbest;
    int i = blockIdx.x, t = threadIdx.x;         // 256 threads
    int lane = t & 31, warp = t >> 5;
    for (int k = t; k < NS; k += 256) sfd[k] = 0.f;
    int degi = g_deg[i];
    if (t < degi){ sic[t] = g_nzc[i*MAXDEG + t]; siv[t] = g_nzv[i*MAXDEG + t]; }
    __syncthreads();
    if (t < degi) sdeg[t] = g_deg[sic[t]];       // all neighbor degrees up front
    __syncthreads();
    // depth-2 software prefetch: (col,val) for iterations jj and jj+1 live in registers
    int   c0 = -1, c1 = -1;
    float v0 = 0.f, v1 = 0.f;
    if (0 < degi && t < sdeg[0]){ c0 = g_nzc[sic[0]*MAXDEG + t]; v0 = g_nzv[sic[0]*MAXDEG + t]; }
    if (1 < degi && t < sdeg[1]){ c1 = g_nzc[sic[1]*MAXDEG + t]; v1 = g_nzv[sic[1]*MAXDEG + t]; }
    for (int jj = 0; jj < degi; jj++){           // ascending-j == dense ascending-k bitwise
        int   c2 = -1; float v2 = 0.f;
        if (jj + 2 < degi && t < sdeg[jj+2]){    // issue next loads before the barrier
            c2 = g_nzc[sic[jj+2]*MAXDEG + t];
            v2 = g_nzv[sic[jj+2]*MAXDEG + t];
        }
        float aij = siv[jj];
        if (c0 >= 0) sfd[c0] = __fmaf_rn(aij, v0, sfd[c0]);  // distinct k within one j
        __syncthreads();
        c0 = c1; v0 = v1; c1 = c2; v1 = v2;
    }
    float sqi = g_sqadj[i];
    unsigned long long lk[16];
    #pragma unroll
    for (int m = 0; m < 16; m++){
        int k = t + 256*m;
        unsigned long long key = ~0ULL;
        if (k < NS && k != i){
            float fd = __fsub_rn(__fadd_rn(sqi, g_sqadj[k]), __fmul_rn(2.f, sfd[k]));
            key = ((unsigned long long)ord_f(fd) << 32) | (unsigned)k;
        }
        lk[m] = key;
    }
    unsigned long long lmin = lk[0];
    #pragma unroll
    for (int m = 1; m < 16; m++) lmin = umin64(lmin, lk[m]);
    for (int r = 0; r < KK; r++){
        unsigned long long b = lmin;
        #pragma unroll
        for (int o = 16; o > 0; o >>= 1) b = umin64(b, __shfl_down_sync(0xffffffffu, b, o));
        if (lane == 0) swin[warp] = b;
        __syncthreads();
        if (t == 0){
            unsigned long long bb = swin[0];
            #pragma unroll
            for (int w = 1; w < 8; w++) bb = umin64(bb, swin[w]);
            sbest = bb;
            g_knn[i*KK + r] = (int)(bb & 0xFFFFFFFFu);
        }
        __syncthreads();
        unsigned long long best = sbest;
        if (lmin == best){                       // unique key (idx embedded): one owner
            #pragma unroll
            for (int m = 0; m < 16; m++) if (lk[m] == best) lk[m] = ~0ULL;
            lmin = lk[0];
            #pragma unroll
            for (int m = 1; m < 16; m++) lmin = umin64(lmin, lk[m]);
        }
        __syncthreads();
    }
}

// ---------------- K8: triangles, warp per pair (XLA matvec reduce for hf@wf2) ----------------
__global__ void __launch_bounds__(256) k_tri(const float* __restrict__ bf1,
                      const float* __restrict__ wf2,
                      float* __restrict__ out){
    __shared__ int   sk[KK];
    __shared__ float sAi[KK];
    __shared__ float sGi[HH];
    __shared__ float sGn[KK][HH+4];              // padded to dodge bank conflicts
    __shared__ float sb[HH], sw[HH];
    int i = blockIdx.x, t = threadIdx.x;         // 256 threads, 8 warps
    int lane = t & 31, warp = t >> 5;
    if (t < KK) sk[t] = g_knn[i*KK + t];
    if (t < HH){ sGi[t] = g_G[i*HH + t]; sb[t] = bf1[t]; sw[t] = wf2[t]; }
    __syncthreads();
    if (t < KK) sAi[t] = g_adj[i*NS + sk[t]];
    for (int q = warp; q < KK; q += 8){
        sGn[q][lane]      = g_G[sk[q]*HH + lane];
        sGn[q][lane+32]   = g_G[sk[q]*HH + lane + 32];
        sGn[q][lane+64]   = g_G[sk[q]*HH + lane + 64];
        sGn[q][lane+96]   = g_G[sk[q]*HH + lane + 96];
    }
    __syncthreads();
    const float third = 1.0f/3.0f;
    #pragma unroll
    for (int it = 0; it < NPAIR/8; it++){        // 15 iterations x 8 warps = 120 pairs
        int p0 = it*8 + warp;
        int p = p0, j = 0;
        while (p >= (KK - 1 - j)){ p -= (KK - 1 - j); j++; }   // triu_indices(16,1) order
        int l = j + 1 + p;
        // hf@wf2: lane partials k=lane+32m (rounded products, sequential adds), butterfly
        float s = 0.f;
        #pragma unroll
        for (int m = 0; m < 4; m++){
            int k = lane + 32*m;
            float pre = (sGi[k] + sGn[j][k] + sGn[l][k]) * third + sb[k];  // value-only path
            float hf  = fmaxf(pre, 0.f);
            s = __fadd_rn(s, __fmul_rn(hf, sw[k]));
        }
        s = warp_red_xla(s);
        if (lane == 0){
            int n1 = sk[j], n2 = sk[l];
            float a12  = g_adj[n1*NS + n2];
            bool valid = a12 > 0.f;
            float prod = __fmul_rn(__fmul_rn(sAi[j], sAi[l]), a12);
            float tpr  = valid ? cbrtf(fmaxf(prod, 1e-9f)) : 0.f;
            float fpr  = valid ? sigmoid_xla(s) : 0.f;
            out[i*NPAIR + p0]        = fpr;
            out[OUTM + i*NPAIR + p0] = tpr;
        }
    }
}

// ---------------- launch ----------------
extern "C" void kernel_launch(void* const* d_in, const int* in_sizes, int n_in,
                              void* d_out, int out_size){
    (void)in_sizes; (void)n_in; (void)out_size;
    const float* x   = (const float*)d_in[0];
    const float* pos = (const float*)d_in[1];
    const float* W1  = (const float*)d_in[2];
    const float* b1  = (const float*)d_in[3];
    const float* w2  = (const float*)d_in[4];
    const float* we  = (const float*)d_in[5];
    const float* Wf1 = (const float*)d_in[6];
    const float* bf1 = (const float*)d_in[7];
    const float* wf2 = (const float*)d_in[8];
    float* out = (float*)d_out;

    k_zero_adj<<<1184, 256>>>();                 // 148 SMs x 8 blocks
    k_probs<<<NN/4, 128>>>(x, W1, b1, w2);       // 2000 blocks
    k_rank_a<<<128, 256>>>();                    // 4 quarters x 32 node-blocks
    k_rank_b<<<32, 256>>>();
    k_gather<<<NS, HH>>>(x, pos, Wf1);
    k_knn_pos<<<125, 128>>>();                   // 125 blocks x (4 quarter-warps x 32 rows)
    k_edges<<<(NS*EK + 7)/8, 256>>>(we);
    k_nzlist<<<NS/8, 256>>>();
    k_fd2knn<<<NS, 256>>>();
    k_tri<<<NS, 256>>>(bf1, wf2, out);
}

// round 13
// speedup vs baseline: 2.7664x; 1.7456x over previous
#include <cuda_runtime.h>
#include <math.h>
#include <stdint.h>

#define NN 8000
#define NS 4000
#define DD 64
#define HH 128
#define EK 15
#define KK 16
#define MAXDEG 256
#define NPAIR 120
#define OUTM (NS*NPAIR)

// ---------------- device scratch (static, no dynamic allocation) ----------------
__device__ __align__(16) float g_adj[NS*NS];          // 64 MB dense symmetric adjacency
__device__ unsigned long long g_key[NN];
__device__ int   g_cnt[NN];
__device__ __align__(16) float g_sx[NS*DD];
__device__ __align__(16) float g_sp[NS*4];            // x,y,z,sq
__device__ float g_G[NS*HH];
__device__ int   g_nbr[NS*EK];
__device__ int   g_deg[NS];
__device__ __align__(16) int   g_nzc[NS*MAXDEG];
__device__ __align__(16) float g_nzv[NS*MAXDEG];
__device__ float g_sqadj[NS];
__device__ int   g_knn[NS*KK];

__device__ __forceinline__ unsigned ord_f(float f){
    unsigned u = __float_as_uint(f);
    return (u & 0x80000000u) ? ~u : (u | 0x80000000u);   // ascending-float -> ascending-uint
}
__device__ __forceinline__ unsigned long long umin64(unsigned long long a, unsigned long long b){
    return a < b ? a : b;
}

// ---- XLA/Eigen fast tanh (f32), bit-exact replication ----
__device__ __forceinline__ float tanh_xla(float x){
    float ax = fabsf(x);
    if (ax < 0.0004f) return x;                           // XLA kCanUseApprox shortcut
    float xc = fminf(fmaxf(x, -7.90531110763549805f), 7.90531110763549805f);
    float x2 = __fmul_rn(xc, xc);
    float p = __fmaf_rn(x2, -2.76076847742355e-16f, 2.00018790482477e-13f);
    p = __fmaf_rn(x2, p, -8.60467152213735e-11f);
    p = __fmaf_rn(x2, p,  5.12229709037114e-08f);
    p = __fmaf_rn(x2, p,  1.48572235717979e-05f);
    p = __fmaf_rn(x2, p,  6.37261928875436e-04f);
    p = __fmaf_rn(x2, p,  4.89352455891786e-03f);
    p = __fmul_rn(p, xc);
    float q = __fmaf_rn(x2, 1.19825839466702e-06f, 1.18534705686654e-04f);
    q = __fmaf_rn(x2, q, 2.26843463243900e-03f);
    q = __fmaf_rn(x2, q, 4.89352518554385e-03f);
    return __fdiv_rn(p, q);
}
// XLA logistic expansion: 0.5 + 0.5 * tanh(0.5 * x)
__device__ __forceinline__ float sigmoid_xla(float v){
    return __fadd_rn(0.5f, __fmul_rn(0.5f, tanh_xla(__fmul_rn(0.5f, v))));
}
// XLA row-reduction warp tail: shfl_down butterfly 16..1, result in lane 0
__device__ __forceinline__ float warp_red_xla(float s){
    #pragma unroll
    for (int o = 16; o > 0; o >>= 1)
        s = __fadd_rn(s, __shfl_down_sync(0xffffffffu, s, o));
    return s;
}

// ---------------- K1: probs = sigmoid_xla(relu(x@W1+b1)@w2), warp per node ----------------
// Also zeroes g_cnt (rank counters) — runs before k_rank_a in stream order.
__global__ void __launch_bounds__(128) k_probs(const float* __restrict__ x,
                        const float* __restrict__ W1,
                        const float* __restrict__ b1, const float* __restrict__ w2){
    __shared__ float xs[4][DD];
    __shared__ float sW1[DD*HH];                // 32 KB
    int warp = threadIdx.x >> 5, lane = threadIdx.x & 31;
    const float4* wsrc = reinterpret_cast<const float4*>(W1);
    float4* wdst = reinterpret_cast<float4*>(sW1);
    #pragma unroll
    for (int u = 0; u < (DD*HH/4)/128; u++)
        wdst[threadIdx.x + 128*u] = wsrc[threadIdx.x + 128*u];
    int n = blockIdx.x*4 + warp;                // 8000 nodes, 4 warps/block, grid=2000
    if (lane == 0) g_cnt[n] = 0;                // reset rank counter for this replay
    xs[warp][lane]      = x[n*DD + lane];
    xs[warp][lane + 32] = x[n*DD + lane + 32];
    __syncthreads();
    float s = 0.f;
    #pragma unroll
    for (int j = 0; j < 4; j++){
        int k = lane + 32*j;
        float h = 0.f;
        #pragma unroll
        for (int d = 0; d < DD; d++) h = __fmaf_rn(xs[warp][d], sW1[d*HH + k], h);
        h = fmaxf(__fadd_rn(h, b1[k]), 0.f);
        float m = __fmul_rn(h, w2[k]);
        s = __fadd_rn(s, m);                    // sequential ascending-j adds
    }
    s = warp_red_xla(s);
    if (lane == 0){
        float p = sigmoid_xla(s);
        g_key[n] = ((unsigned long long)ord_f(p) << 32) | (unsigned)(NN - 1 - n); // tie->lower n
    }
}

// ---------------- K2a: partial exact ranking (quarter scans, int-atomic merge) ----------------
__global__ void __launch_bounds__(256) k_rank_a(){
    __shared__ unsigned long long sk[256];
    int qt = blockIdx.x >> 5;                   // quarter 0..3
    int nb = blockIdx.x & 31;                   // node block 0..31
    int n = nb*256 + threadIdx.x;               // 0..8191
    unsigned long long my = (n < NN) ? g_key[n] : 0ULL;
    int cnt = 0;
    int lo = qt*(NN/4), hi = lo + NN/4;         // 2000-wide key range
    for (int base = lo; base < hi; base += 256){
        int idx = base + threadIdx.x;
        sk[threadIdx.x] = (idx < hi) ? g_key[idx] : 0ULL;
        __syncthreads();
        int lim = min(256, hi - base);
        for (int k = 0; k < lim; k++) cnt += (sk[k] > my) ? 1 : 0;
        __syncthreads();
    }
    if (n < NN && cnt > 0) atomicAdd(&g_cnt[n], cnt);   // int add: order-independent exact
}

// ---------------- K2b+K3 fused: each selected node writes its own row ----------------
// warp per node: node n with rank c < NS writes sx/sp row c and computes G row c.
// G chain bits identical to prior k_gather: fma d=0..63 then c=0..2, same operand values.
__global__ void __launch_bounds__(256) k_sel_gather(const float* __restrict__ x,
                         const float* __restrict__ pos,
                         const float* __restrict__ Wf1){
    __shared__ float xs[8][DD];
    int warp = threadIdx.x >> 5, lane = threadIdx.x & 31;
    int n = blockIdx.x*8 + warp;                // 1000 blocks x 8 warps = 8000 nodes
    int c = g_cnt[n];
    if (c >= NS) return;                        // not selected: whole warp exits
    int r = c;
    float x0 = x[n*DD + lane], x1 = x[n*DD + lane + 32];
    xs[warp][lane] = x0; xs[warp][lane + 32] = x1;
    g_sx[r*DD + lane] = x0; g_sx[r*DD + lane + 32] = x1;
    float pv = (lane < 3) ? pos[n*3 + lane] : 0.f;
    if (lane < 3) g_sp[r*4 + lane] = pv;
    float ppx = __shfl_sync(0xffffffffu, pv, 0);
    float ppy = __shfl_sync(0xffffffffu, pv, 1);
    float ppz = __shfl_sync(0xffffffffu, pv, 2);
    if (lane == 0){
        // sq = (x^2 + y^2) + z^2, squares rounded separately (square-then-reduce, NO fma)
        float sq = __fadd_rn(__fadd_rn(__fmul_rn(ppx,ppx), __fmul_rn(ppy,ppy)),
                             __fmul_rn(ppz,ppz));
        g_sp[r*4 + 3] = sq;
    }
    __syncwarp();
    float g0 = 0.f, g1 = 0.f, g2 = 0.f, g3 = 0.f;
    int t0 = lane, t1 = lane + 32, t2 = lane + 64, t3 = lane + 96;
    #pragma unroll
    for (int d = 0; d < DD; d++){
        float v = xs[warp][d];
        const float* wrow = &Wf1[d*HH];
        g0 = fmaf(v, wrow[t0], g0);
        g1 = fmaf(v, wrow[t1], g1);
        g2 = fmaf(v, wrow[t2], g2);
        g3 = fmaf(v, wrow[t3], g3);
    }
    {
        const float* wrow = &Wf1[DD*HH];
        g0 = fmaf(ppx, wrow[t0], g0); g1 = fmaf(ppx, wrow[t1], g1);
        g2 = fmaf(ppx, wrow[t2], g2); g3 = fmaf(ppx, wrow[t3], g3);
        wrow += HH;
        g0 = fmaf(ppy, wrow[t0], g0); g1 = fmaf(ppy, wrow[t1], g1);
        g2 = fmaf(ppy, wrow[t2], g2); g3 = fmaf(ppy, wrow[t3], g3);
        wrow += HH;
        g0 = fmaf(ppz, wrow[t0], g0); g1 = fmaf(ppz, wrow[t1], g1);
        g2 = fmaf(ppz, wrow[t2], g2); g3 = fmaf(ppz, wrow[t3], g3);
    }
    g_G[r*HH + t0] = g0; g_G[r*HH + t1] = g1;
    g_G[r*HH + t2] = g2; g_G[r*HH + t3] = g3;
}

// ---------------- K4: 15-NN over positions — warp per EIGHTH, lane per row ----------------
// Index-range partition into 8 disjoint ascending ranges; per-warp exact (d2,idx)-lex
// top-15 (strict-<, position-count insertion, ties after), 8-way lex merge of sorted
// lists == lax.top_k global selection (keys unique: idx embedded).
#define INSERT15(D2, CC) do{ \
    int pos = 0; \
    _Pragma("unroll") \
    for (int s = 0; s < EK; s++) pos += (bd[s] <= (D2)) ? 1 : 0; \
    _Pragma("unroll") \
    for (int s = EK-1; s > 0; s--){ if (s > pos){ bd[s] = bd[s-1]; bi[s] = bi[s-1]; } } \
    _Pragma("unroll") \
    for (int s = 0; s < EK; s++){ if (s == pos){ bd[s] = (D2); bi[s] = (CC); } } \
}while(0)

__global__ void __launch_bounds__(256) k_knn_pos(){
    __shared__ float4 tile[8][132];                       // per-warp staging
    __shared__ unsigned long long lists[8][32][EK];       // 30.7 KB
    int lane = threadIdx.x & 31, q = threadIdx.x >> 5;    // warp == eighth
    int row = blockIdx.x*32 + lane;                       // 125 blocks x 32 rows
    float4 m = *reinterpret_cast<const float4*>(&g_sp[row*4]);
    float px = m.x, py = m.y, pz = m.z, sqi = m.w;
    const int QW = NS/8;                                   // 500
    const int qlo = q*QW;
    float bd[EK]; int bi[EK];
    #pragma unroll
    for (int s = 0; s < EK; s++){ bd[s] = 3.4e38f; bi[s] = 0; }
    for (int t0 = 0; t0 < QW; t0 += 128){
        int nload = min(128, QW - t0);                     // 128,128,128,116 (even)
        for (int u = lane; u < nload; u += 32)
            tile[q][u] = *reinterpret_cast<const float4*>(&g_sp[(qlo + t0 + u)*4]);
        __syncwarp();
        for (int u = 0; u < nload; u += 2){
            int c0 = qlo + t0 + u, c1 = c0 + 1;
            float4 q0 = tile[q][u], q1 = tile[q][u+1];
            // acc=0; fma k=0,1,2 -> fma(z,qz, fma(y,qy, round(x*qx)))  [pass bits]
            float dot0 = __fmaf_rn(pz, q0.z, __fmaf_rn(py, q0.y, __fmul_rn(px, q0.x)));
            float dot1 = __fmaf_rn(pz, q1.z, __fmaf_rn(py, q1.y, __fmul_rn(px, q1.x)));
            float d20  = __fsub_rn(__fadd_rn(sqi, q0.w), __fmul_rn(2.f, dot0));
            float d21  = __fsub_rn(__fadd_rn(sqi, q1.w), __fmul_rn(2.f, dot1));
            if (c0 != row && d20 < bd[EK-1]) INSERT15(d20, c0);   // ascending order kept
            if (c1 != row && d21 < bd[EK-1]) INSERT15(d21, c1);
        }
        __syncwarp();
    }
    #pragma unroll
    for (int s = 0; s < EK; s++)
        lists[q][lane][s] = ((unsigned long long)ord_f(bd[s]) << 32) | (unsigned)bi[s];
    __syncthreads();
    if (threadIdx.x < 32){
        int r2 = blockIdx.x*32 + threadIdx.x;
        int h[8];
        #pragma unroll
        for (int w = 0; w < 8; w++) h[w] = 0;
        #pragma unroll
        for (int r = 0; r < EK; r++){
            unsigned long long best = ~0ULL; int bw = 0;
            #pragma unroll
            for (int w = 0; w < 8; w++){
                unsigned long long v = (h[w] < EK) ? lists[w][threadIdx.x][h[w]] : ~0ULL;
                if (v < best){ best = v; bw = w; }
            }
            h[bw]++;
            g_nbr[r2*EK + r] = (int)(best & 0xFFFFFFFFu);
        }
    }
}

// ---------------- K0: zero adjacency (after knn, before edges) ----------------
__global__ void __launch_bounds__(256) k_zero_adj(){
    float4 z = make_float4(0.f,0.f,0.f,0.f);
    float4* p = reinterpret_cast<float4*>(g_adj);
    const int n4 = (NS*NS)/4;
    for (int i = blockIdx.x*blockDim.x + threadIdx.x; i < n4; i += gridDim.x*blockDim.x)
        p[i] = z;
}

// ---------------- K5: edge probs, warp per edge (XLA mult+row-reduce shape) ----------------
__global__ void __launch_bounds__(256) k_edges(const float* __restrict__ we){
    int e = blockIdx.x*8 + (threadIdx.x >> 5);
    int lane = threadIdx.x & 31;
    if (e >= NS*EK) return;
    int i = e / EK;
    int j = g_nbr[e];
    const float* a = &g_sx[i*DD];
    const float* b = &g_sx[j*DD];
    // z_k = round(a_k*b_k); m_k = round(z_k*w_k); lane partial = m_lane + m_{lane+32}
    float m0 = __fmul_rn(__fmul_rn(a[lane],      b[lane]),      we[lane]);
    float m1 = __fmul_rn(__fmul_rn(a[lane + 32], b[lane + 32]), we[lane + 32]);
    float s  = __fadd_rn(m0, m1);
    s = warp_red_xla(s);
    if (lane == 0){
        float ep = sigmoid_xla(s);
        g_adj[i*NS + j] = ep;    // symmetric/duplicate writes identical bits: race-free
        g_adj[j*NS + i] = ep;
    }
}

// ---------------- K6: per-row sparse nz lists (column-ascending, deterministic) ----------------
__global__ void __launch_bounds__(256) k_nzlist(){
    int wid  = (blockIdx.x*blockDim.x + threadIdx.x) >> 5;
    int lane = threadIdx.x & 31;
    if (wid >= NS) return;
    int cnt = 0;
    for (int base = 0; base < NS; base += 32){
        float v = g_adj[wid*NS + base + lane];
        unsigned m = __ballot_sync(0xffffffffu, v != 0.f);
        if (v != 0.f){
            int pos = cnt + __popc(m & ((1u << lane) - 1u));
            if (pos < MAXDEG){ g_nzc[wid*MAXDEG + pos] = base + lane; g_nzv[wid*MAXDEG + pos] = v; }
        }
        cnt += __popc(m);
    }
    int deg = min(cnt, MAXDEG);
    if (lane == 0){
        g_deg[wid] = deg;
        // ||row||^2: ascending-column sequential (zeros contribute exact 0 in any order)
        float s = 0.f;
        for (int t = 0; t < deg; t++){
            float v = g_nzv[wid*MAXDEG + t];
            s = __fadd_rn(s, __fmul_rn(v, v));
        }
        g_sqadj[wid] = s;
    }
}

// ---------------- K7: sparse adj@adjT row, fd2, exact 16-NN (prefetch pipeline) ----------------
__global__ void __launch_bounds__(256) k_fd2knn(){
    __shared__ float sfd[NS];                    // 16 KB accumulate buffer
    __shared__ int   sic[MAXDEG];
    __shared__ float siv[MAXDEG];
    __shared__ int   sdeg[MAXDEG];
    __shared__ unsigned long long swin[8];
    __shared__ unsigned long long sbest;
    int i = blockIdx.x, t = threadIdx.x;         // 256 threads
    int lane = t & 31, warp = t >> 5;
    for (int k = t; k < NS; k += 256) sfd[k] = 0.f;
    int degi = g_deg[i];
    if (t < degi){ sic[t] = g_nzc[i*MAXDEG + t]; siv[t] = g_nzv[i*MAXDEG + t]; }
    __syncthreads();
    if (t < degi) sdeg[t] = g_deg[sic[t]];       // all neighbor degrees up front
    __syncthreads();
    // depth-2 software prefetch: (col,val) for iterations jj and jj+1 live in registers
    int   c0 = -1, c1 = -1;
    float v0 = 0.f, v1 = 0.f;
    if (0 < degi && t < sdeg[0]){ c0 = g_nzc[sic[0]*MAXDEG + t]; v0 = g_nzv[sic[0]*MAXDEG + t]; }
    if (1 < degi && t < sdeg[1]){ c1 = g_nzc[sic[1]*MAXDEG + t]; v1 = g_nzv[sic[1]*MAXDEG + t]; }
    for (int jj = 0; jj < degi; jj++){           // ascending-j == dense ascending-k bitwise
        int   c2 = -1; float v2 = 0.f;
        if (jj + 2 < degi && t < sdeg[jj+2]){    // issue next loads before the barrier
            c2 = g_nzc[sic[jj+2]*MAXDEG + t];
            v2 = g_nzv[sic[jj+2]*MAXDEG + t];
        }
        float aij = siv[jj];
        if (c0 >= 0) sfd[c0] = __fmaf_rn(aij, v0, sfd[c0]);  // distinct k within one j
        __syncthreads();
        c0 = c1; v0 = v1; c1 = c2; v1 = v2;
    }
    float sqi = g_sqadj[i];
    unsigned long long lk[16];
    #pragma unroll
    for (int m = 0; m < 16; m++){
        int k = t + 256*m;
        unsigned long long key = ~0ULL;
        if (k < NS && k != i){
            float fd = __fsub_rn(__fadd_rn(sqi, g_sqadj[k]), __fmul_rn(2.f, sfd[k]));
            key = ((unsigned long long)ord_f(fd) << 32) | (unsigned)k;
        }
        lk[m] = key;
    }
    unsigned long long lmin = lk[0];
    #pragma unroll
    for (int m = 1; m < 16; m++) lmin = umin64(lmin, lk[m]);
    for (int r = 0; r < KK; r++){
        unsigned long long b = lmin;
        #pragma unroll
        for (int o = 16; o > 0; o >>= 1) b = umin64(b, __shfl_down_sync(0xffffffffu, b, o));
        if (lane == 0) swin[warp] = b;
        __syncthreads();
        if (t == 0){
            unsigned long long bb = swin[0];
            #pragma unroll
            for (int w = 1; w < 8; w++) bb = umin64(bb, swin[w]);
            sbest = bb;
            g_knn[i*KK + r] = (int)(bb & 0xFFFFFFFFu);
        }
        __syncthreads();
        unsigned long long best = sbest;
        if (lmin == best){                       // unique key (idx embedded): one owner
            #pragma unroll
            for (int m = 0; m < 16; m++) if (lk[m] == best) lk[m] = ~0ULL;
            lmin = lk[0];
            #pragma unroll
            for (int m = 1; m < 16; m++) lmin = umin64(lmin, lk[m]);
        }
        __syncthreads();
    }
}

// ---------------- K8: triangles, warp per pair (XLA matvec reduce for hf@wf2) ----------------
__global__ void __launch_bounds__(256) k_tri(const float* __restrict__ bf1,
                      const float* __restrict__ wf2,
                      float* __restrict__ out){
    __shared__ int   sk[KK];
    __shared__ float sAi[KK];
    __shared__ float sGi[HH];
    __shared__ float sGn[KK][HH+4];              // padded to dodge bank conflicts
    __shared__ float sb[HH], sw[HH];
    int i = blockIdx.x, t = threadIdx.x;         // 256 threads, 8 warps
    int lane = t & 31, warp = t >> 5;
    if (t < KK) sk[t] = g_knn[i*KK + t];
    if (t < HH){ sGi[t] = g_G[i*HH + t]; sb[t] = bf1[t]; sw[t] = wf2[t]; }
    __syncthreads();
    if (t < KK) sAi[t] = g_adj[i*NS + sk[t]];
    for (int q = warp; q < KK; q += 8){
        sGn[q][lane]      = g_G[sk[q]*HH + lane];
        sGn[q][lane+32]   = g_G[sk[q]*HH + lane + 32];
        sGn[q][lane+64]   = g_G[sk[q]*HH + lane + 64];
        sGn[q][lane+96]   = g_G[sk[q]*HH + lane + 96];
    }
    __syncthreads();
    const float third = 1.0f/3.0f;
    #pragma unroll
    for (int it = 0; it < NPAIR/8; it++){        // 15 iterations x 8 warps = 120 pairs
        int p0 = it*8 + warp;
        int p = p0, j = 0;
        while (p >= (KK - 1 - j)){ p -= (KK - 1 - j); j++; }   // triu_indices(16,1) order
        int l = j + 1 + p;
        // hf@wf2: lane partials k=lane+32m (rounded products, sequential adds), butterfly
        float s = 0.f;
        #pragma unroll
        for (int m = 0; m < 4; m++){
            int k = lane + 32*m;
            float pre = (sGi[k] + sGn[j][k] + sGn[l][k]) * third + sb[k];  // value-only path
            float hf  = fmaxf(pre, 0.f);
            s = __fadd_rn(s, __fmul_rn(hf, sw[k]));
        }
        s = warp_red_xla(s);
        if (lane == 0){
            int n1 = sk[j], n2 = sk[l];
            float a12  = g_adj[n1*NS + n2];
            bool valid = a12 > 0.f;
            float prod = __fmul_rn(__fmul_rn(sAi[j], sAi[l]), a12);
            float tpr  = valid ? cbrtf(fmaxf(prod, 1e-9f)) : 0.f;
            float fpr  = valid ? sigmoid_xla(s) : 0.f;
            out[i*NPAIR + p0]        = fpr;
            out[OUTM + i*NPAIR + p0] = tpr;
        }
    }
}

// ---------------- launch ----------------
extern "C" void kernel_launch(void* const* d_in, const int* in_sizes, int n_in,
                              void* d_out, int out_size){
    (void)in_sizes; (void)n_in; (void)out_size;
    const float* x   = (const float*)d_in[0];
    const float* pos = (const float*)d_in[1];
    const float* W1  = (const float*)d_in[2];
    const float* b1  = (const float*)d_in[3];
    const float* w2  = (const float*)d_in[4];
    const float* we  = (const float*)d_in[5];
    const float* Wf1 = (const float*)d_in[6];
    const float* bf1 = (const float*)d_in[7];
    const float* wf2 = (const float*)d_in[8];
    float* out = (float*)d_out;

    k_probs<<<NN/4, 128>>>(x, W1, b1, w2);       // idx 0: keys + cnt reset
    k_rank_a<<<128, 256>>>();                    // idx 1
    k_sel_gather<<<NN/8, 256>>>(x, pos, Wf1);    // idx 2: fused rank_b+gather
    k_knn_pos<<<125, 256>>>();                   // idx 3  <- ncu capture target
    k_zero_adj<<<1184, 256>>>();                 // idx 4 (before edges; legal position)
    k_edges<<<(NS*EK + 7)/8, 256>>>(we);         // idx 5
    k_nzlist<<<NS/8, 256>>>();                   // idx 6
    k_fd2knn<<<NS, 256>>>();                     // idx 7
    k_tri<<<NS, 256>>>(bf1, wf2, out);           // idx 8
}

// round 14
// speedup vs baseline: 2.9361x; 1.0613x over previous
#include <cuda_runtime.h>
#include <math.h>
#include <stdint.h>

#define NN 8000
#define NS 4000
#define DD 64
#define HH 128
#define EK 15
#define KK 16
#define MAXDEG 256
#define NPAIR 120
#define OUTM (NS*NPAIR)

// ---------------- device scratch (static, no dynamic allocation) ----------------
__device__ __align__(16) float g_adj[NS*NS];          // 64 MB dense symmetric adjacency
__device__ unsigned long long g_key[NN];
__device__ int   g_cnt[NN];
__device__ __align__(16) float g_sx[NS*DD];
__device__ __align__(16) float g_sp[NS*4];            // x,y,z,sq
__device__ float g_G[NS*HH];
__device__ int   g_nbr[NS*EK];
__device__ int   g_deg[NS];
__device__ __align__(16) int   g_nzc[NS*MAXDEG];
__device__ __align__(16) float g_nzv[NS*MAXDEG];
__device__ float g_sqadj[NS];
__device__ int   g_knn[NS*KK];

__device__ __forceinline__ unsigned ord_f(float f){
    unsigned u = __float_as_uint(f);
    return (u & 0x80000000u) ? ~u : (u | 0x80000000u);   // ascending-float -> ascending-uint
}
__device__ __forceinline__ unsigned long long umin64(unsigned long long a, unsigned long long b){
    return a < b ? a : b;
}

// ---- XLA/Eigen fast tanh (f32), bit-exact replication ----
__device__ __forceinline__ float tanh_xla(float x){
    float ax = fabsf(x);
    if (ax < 0.0004f) return x;                           // XLA kCanUseApprox shortcut
    float xc = fminf(fmaxf(x, -7.90531110763549805f), 7.90531110763549805f);
    float x2 = __fmul_rn(xc, xc);
    float p = __fmaf_rn(x2, -2.76076847742355e-16f, 2.00018790482477e-13f);
    p = __fmaf_rn(x2, p, -8.60467152213735e-11f);
    p = __fmaf_rn(x2, p,  5.12229709037114e-08f);
    p = __fmaf_rn(x2, p,  1.48572235717979e-05f);
    p = __fmaf_rn(x2, p,  6.37261928875436e-04f);
    p = __fmaf_rn(x2, p,  4.89352455891786e-03f);
    p = __fmul_rn(p, xc);
    float q = __fmaf_rn(x2, 1.19825839466702e-06f, 1.18534705686654e-04f);
    q = __fmaf_rn(x2, q, 2.26843463243900e-03f);
    q = __fmaf_rn(x2, q, 4.89352518554385e-03f);
    return __fdiv_rn(p, q);
}
// XLA logistic expansion: 0.5 + 0.5 * tanh(0.5 * x)
__device__ __forceinline__ float sigmoid_xla(float v){
    return __fadd_rn(0.5f, __fmul_rn(0.5f, tanh_xla(__fmul_rn(0.5f, v))));
}
// XLA row-reduction warp tail: shfl_down butterfly 16..1, result in lane 0
__device__ __forceinline__ float warp_red_xla(float s){
    #pragma unroll
    for (int o = 16; o > 0; o >>= 1)
        s = __fadd_rn(s, __shfl_down_sync(0xffffffffu, s, o));
    return s;
}

// ---------------- K1: probs = sigmoid_xla(relu(x@W1+b1)@w2), warp per node ----------------
// Also zeroes g_cnt (rank counters) — runs before k_rank_a in stream order.
__global__ void __launch_bounds__(128) k_probs(const float* __restrict__ x,
                        const float* __restrict__ W1,
                        const float* __restrict__ b1, const float* __restrict__ w2){
    __shared__ float xs[4][DD];
    __shared__ float sW1[DD*HH];                // 32 KB
    int warp = threadIdx.x >> 5, lane = threadIdx.x & 31;
    const float4* wsrc = reinterpret_cast<const float4*>(W1);
    float4* wdst = reinterpret_cast<float4*>(sW1);
    #pragma unroll
    for (int u = 0; u < (DD*HH/4)/128; u++)
        wdst[threadIdx.x + 128*u] = wsrc[threadIdx.x + 128*u];
    int n = blockIdx.x*4 + warp;                // 8000 nodes, 4 warps/block, grid=2000
    if (lane == 0) g_cnt[n] = 0;                // reset rank counter for this replay
    xs[warp][lane]      = x[n*DD + lane];
    xs[warp][lane + 32] = x[n*DD + lane + 32];
    __syncthreads();
    float s = 0.f;
    #pragma unroll
    for (int j = 0; j < 4; j++){
        int k = lane + 32*j;
        float h = 0.f;
        #pragma unroll
        for (int d = 0; d < DD; d++) h = __fmaf_rn(xs[warp][d], sW1[d*HH + k], h);
        h = fmaxf(__fadd_rn(h, b1[k]), 0.f);
        float m = __fmul_rn(h, w2[k]);
        s = __fadd_rn(s, m);                    // sequential ascending-j adds
    }
    s = warp_red_xla(s);
    if (lane == 0){
        float p = sigmoid_xla(s);
        g_key[n] = ((unsigned long long)ord_f(p) << 32) | (unsigned)(NN - 1 - n); // tie->lower n
    }
}

// ---------------- K2a: partial exact ranking (quarter scans, int-atomic merge) ----------------
__global__ void __launch_bounds__(256) k_rank_a(){
    __shared__ unsigned long long sk[256];
    int qt = blockIdx.x >> 5;                   // quarter 0..3
    int nb = blockIdx.x & 31;                   // node block 0..31
    int n = nb*256 + threadIdx.x;               // 0..8191
    unsigned long long my = (n < NN) ? g_key[n] : 0ULL;
    int cnt = 0;
    int lo = qt*(NN/4), hi = lo + NN/4;         // 2000-wide key range
    for (int base = lo; base < hi; base += 256){
        int idx = base + threadIdx.x;
        sk[threadIdx.x] = (idx < hi) ? g_key[idx] : 0ULL;
        __syncthreads();
        int lim = min(256, hi - base);
        for (int k = 0; k < lim; k++) cnt += (sk[k] > my) ? 1 : 0;
        __syncthreads();
    }
    if (n < NN && cnt > 0) atomicAdd(&g_cnt[n], cnt);   // int add: order-independent exact
}

// ---------------- K2b+K3 fused: each selected node writes its own row ----------------
__global__ void __launch_bounds__(256) k_sel_gather(const float* __restrict__ x,
                         const float* __restrict__ pos,
                         const float* __restrict__ Wf1){
    __shared__ float xs[8][DD];
    int warp = threadIdx.x >> 5, lane = threadIdx.x & 31;
    int n = blockIdx.x*8 + warp;                // 1000 blocks x 8 warps = 8000 nodes
    int c = g_cnt[n];
    if (c >= NS) return;                        // not selected: whole warp exits
    int r = c;
    float x0 = x[n*DD + lane], x1 = x[n*DD + lane + 32];
    xs[warp][lane] = x0; xs[warp][lane + 32] = x1;
    g_sx[r*DD + lane] = x0; g_sx[r*DD + lane + 32] = x1;
    float pv = (lane < 3) ? pos[n*3 + lane] : 0.f;
    if (lane < 3) g_sp[r*4 + lane] = pv;
    float ppx = __shfl_sync(0xffffffffu, pv, 0);
    float ppy = __shfl_sync(0xffffffffu, pv, 1);
    float ppz = __shfl_sync(0xffffffffu, pv, 2);
    if (lane == 0){
        // sq = (x^2 + y^2) + z^2, squares rounded separately (square-then-reduce, NO fma)
        float sq = __fadd_rn(__fadd_rn(__fmul_rn(ppx,ppx), __fmul_rn(ppy,ppy)),
                             __fmul_rn(ppz,ppz));
        g_sp[r*4 + 3] = sq;
    }
    __syncwarp();
    float g0 = 0.f, g1 = 0.f, g2 = 0.f, g3 = 0.f;
    int t0 = lane, t1 = lane + 32, t2 = lane + 64, t3 = lane + 96;
    #pragma unroll
    for (int d = 0; d < DD; d++){
        float v = xs[warp][d];
        const float* wrow = &Wf1[d*HH];
        g0 = fmaf(v, wrow[t0], g0);
        g1 = fmaf(v, wrow[t1], g1);
        g2 = fmaf(v, wrow[t2], g2);
        g3 = fmaf(v, wrow[t3], g3);
    }
    {
        const float* wrow = &Wf1[DD*HH];
        g0 = fmaf(ppx, wrow[t0], g0); g1 = fmaf(ppx, wrow[t1], g1);
        g2 = fmaf(ppx, wrow[t2], g2); g3 = fmaf(ppx, wrow[t3], g3);
        wrow += HH;
        g0 = fmaf(ppy, wrow[t0], g0); g1 = fmaf(ppy, wrow[t1], g1);
        g2 = fmaf(ppy, wrow[t2], g2); g3 = fmaf(ppy, wrow[t3], g3);
        wrow += HH;
        g0 = fmaf(ppz, wrow[t0], g0); g1 = fmaf(ppz, wrow[t1], g1);
        g2 = fmaf(ppz, wrow[t2], g2); g3 = fmaf(ppz, wrow[t3], g3);
    }
    g_G[r*HH + t0] = g0; g_G[r*HH + t1] = g1;
    g_G[r*HH + t2] = g2; g_G[r*HH + t3] = g3;
}

// ---------------- K4: 15-NN — warp per row, lane per 1/32 slice, branch-free insert ----------------
// Exact lax.top_k semantics preserved: disjoint ascending index slices per lane; per-lane
// (d2,idx)-lex top-15 via pos-count insertion (ties -> after, i.e. lower idx first);
// self/failed candidates map to pos=15 == natural no-op; 32-way merge of lex-sorted
// register lists via u64 butterfly-min (keys unique: idx embedded).
__global__ void __launch_bounds__(256) k_knn_pos(){
    int lane = threadIdx.x & 31, wrp = threadIdx.x >> 5;
    int row = blockIdx.x*8 + wrp;                 // 500 blocks x 8 rows
    float4 m = *reinterpret_cast<const float4*>(&g_sp[row*4]);
    float px = m.x, py = m.y, pz = m.z, sqi = m.w;
    const int S = NS/32;                          // 125 candidates per lane
    const int lo = lane*S;
    const float INFV = __int_as_float(0x7f800000);
    float bd[EK]; int bi[EK];
    #pragma unroll
    for (int s = 0; s < EK; s++){ bd[s] = 3.4e38f; bi[s] = 0; }
    #pragma unroll 2
    for (int u = 0; u < S; u++){
        int c = lo + u;
        float4 q = *reinterpret_cast<const float4*>(&g_sp[c*4]);
        // acc=0; fma k=0,1,2 -> fma(z,qz, fma(y,qy, round(x*qx)))  [pass bits]
        float dot = __fmaf_rn(pz, q.z, __fmaf_rn(py, q.y, __fmul_rn(px, q.x)));
        float d2  = __fsub_rn(__fadd_rn(sqi, q.w), __fmul_rn(2.f, dot));
        d2 = (c == row) ? INFV : d2;              // self -> pos 15 -> no-op
        int pos = 0;
        #pragma unroll
        for (int s = 0; s < EK; s++) pos += (bd[s] <= d2) ? 1 : 0;   // ties -> after
        #pragma unroll
        for (int s = EK-1; s > 0; s--){ if (s > pos){ bd[s] = bd[s-1]; bi[s] = bi[s-1]; } }
        #pragma unroll
        for (int s = 0; s < EK; s++){ if (s == pos){ bd[s] = d2; bi[s] = c; } }
    }
    // 32-way merge of per-lane sorted lists (registers only)
    unsigned long long head = ((unsigned long long)ord_f(bd[0]) << 32) | (unsigned)bi[0];
    #pragma unroll
    for (int r = 0; r < EK; r++){
        unsigned long long mn = head;
        #pragma unroll
        for (int o = 16; o > 0; o >>= 1)
            mn = umin64(mn, __shfl_xor_sync(0xffffffffu, mn, o));
        if (head == mn){                          // unique keys: exactly one winner
            #pragma unroll
            for (int s = 0; s < EK-1; s++){ bd[s] = bd[s+1]; bi[s] = bi[s+1]; }
            bd[EK-1] = INFV; bi[EK-1] = 0;        // sentinel, can never win
        }
        head = ((unsigned long long)ord_f(bd[0]) << 32) | (unsigned)bi[0];
        if (lane == r) g_nbr[row*EK + r] = (int)(mn & 0xFFFFFFFFu);
    }
}

// ---------------- K0: zero adjacency (after knn, before edges) ----------------
__global__ void __launch_bounds__(256) k_zero_adj(){
    float4 z = make_float4(0.f,0.f,0.f,0.f);
    float4* p = reinterpret_cast<float4*>(g_adj);
    const int n4 = (NS*NS)/4;
    for (int i = blockIdx.x*blockDim.x + threadIdx.x; i < n4; i += gridDim.x*blockDim.x)
        p[i] = z;
}

// ---------------- K5: edge probs, warp per edge (XLA mult+row-reduce shape) ----------------
__global__ void __launch_bounds__(256) k_edges(const float* __restrict__ we){
    int e = blockIdx.x*8 + (threadIdx.x >> 5);
    int lane = threadIdx.x & 31;
    if (e >= NS*EK) return;
    int i = e / EK;
    int j = g_nbr[e];
    const float* a = &g_sx[i*DD];
    const float* b = &g_sx[j*DD];
    // z_k = round(a_k*b_k); m_k = round(z_k*w_k); lane partial = m_lane + m_{lane+32}
    float m0 = __fmul_rn(__fmul_rn(a[lane],      b[lane]),      we[lane]);
    float m1 = __fmul_rn(__fmul_rn(a[lane + 32], b[lane + 32]), we[lane + 32]);
    float s  = __fadd_rn(m0, m1);
    s = warp_red_xla(s);
    if (lane == 0){
        float ep = sigmoid_xla(s);
        g_adj[i*NS + j] = ep;    // symmetric/duplicate writes identical bits: race-free
        g_adj[j*NS + i] = ep;
    }
}

// ---------------- K6: per-row sparse nz lists (column-ascending, deterministic) ----------------
__global__ void __launch_bounds__(256) k_nzlist(){
    int wid  = (blockIdx.x*blockDim.x + threadIdx.x) >> 5;
    int lane = threadIdx.x & 31;
    if (wid >= NS) return;
    int cnt = 0;
    for (int base = 0; base < NS; base += 32){
        float v = g_adj[wid*NS + base + lane];
        unsigned m = __ballot_sync(0xffffffffu, v != 0.f);
        if (v != 0.f){
            int pos = cnt + __popc(m & ((1u << lane) - 1u));
            if (pos < MAXDEG){ g_nzc[wid*MAXDEG + pos] = base + lane; g_nzv[wid*MAXDEG + pos] = v; }
        }
        cnt += __popc(m);
    }
    int deg = min(cnt, MAXDEG);
    if (lane == 0){
        g_deg[wid] = deg;
        // ||row||^2: ascending-column sequential (zeros contribute exact 0 in any order)
        float s = 0.f;
        for (int t = 0; t < deg; t++){
            float v = g_nzv[wid*MAXDEG + t];
            s = __fadd_rn(s, __fmul_rn(v, v));
        }
        g_sqadj[wid] = s;
    }
}

// ---------------- K7: sparse adj@adjT row, fd2, exact 16-NN (prefetch pipeline) ----------------
__global__ void __launch_bounds__(256) k_fd2knn(){
    __shared__ float sfd[NS];                    // 16 KB accumulate buffer
    __shared__ int   sic[MAXDEG];
    __shared__ float siv[MAXDEG];
    __shared__ int   sdeg[MAXDEG];
    __shared__ unsigned long long swin[8];
    __shared__ unsigned long long sbest;
    int i = blockIdx.x, t = threadIdx.x;         // 256 threads
    int lane = t & 31, warp = t >> 5;
    for (int k = t; k < NS; k += 256) sfd[k] = 0.f;
    int degi = g_deg[i];
    if (t < degi){ sic[t] = g_nzc[i*MAXDEG + t]; siv[t] = g_nzv[i*MAXDEG + t]; }
    __syncthreads();
    if (t < degi) sdeg[t] = g_deg[sic[t]];       // all neighbor degrees up front
    __syncthreads();
    // depth-2 software prefetch: (col,val) for iterations jj and jj+1 live in registers
    int   c0 = -1, c1 = -1;
    float v0 = 0.f, v1 = 0.f;
    if (0 < degi && t < sdeg[0]){ c0 = g_nzc[sic[0]*MAXDEG + t]; v0 = g_nzv[sic[0]*MAXDEG + t]; }
    if (1 < degi && t < sdeg[1]){ c1 = g_nzc[sic[1]*MAXDEG + t]; v1 = g_nzv[sic[1]*MAXDEG + t]; }
    for (int jj = 0; jj < degi; jj++){           // ascending-j == dense ascending-k bitwise
        int   c2 = -1; float v2 = 0.f;
        if (jj + 2 < degi && t < sdeg[jj+2]){    // issue next loads before the barrier
            c2 = g_nzc[sic[jj+2]*MAXDEG + t];
            v2 = g_nzv[sic[jj+2]*MAXDEG + t];
        }
        float aij = siv[jj];
        if (c0 >= 0) sfd[c0] = __fmaf_rn(aij, v0, sfd[c0]);  // distinct k within one j
        __syncthreads();
        c0 = c1; v0 = v1; c1 = c2; v1 = v2;
    }
    float sqi = g_sqadj[i];
    unsigned long long lk[16];
    #pragma unroll
    for (int m = 0; m < 16; m++){
        int k = t + 256*m;
        unsigned long long key = ~0ULL;
        if (k < NS && k != i){
            float fd = __fsub_rn(__fadd_rn(sqi, g_sqadj[k]), __fmul_rn(2.f, sfd[k]));
            key = ((unsigned long long)ord_f(fd) << 32) | (unsigned)k;
        }
        lk[m] = key;
    }
    unsigned long long lmin = lk[0];
    #pragma unroll
    for (int m = 1; m < 16; m++) lmin = umin64(lmin, lk[m]);
    for (int r = 0; r < KK; r++){
        unsigned long long b = lmin;
        #pragma unroll
        for (int o = 16; o > 0; o >>= 1) b = umin64(b, __shfl_down_sync(0xffffffffu, b, o));
        if (lane == 0) swin[warp] = b;
        __syncthreads();
        if (t == 0){
            unsigned long long bb = swin[0];
            #pragma unroll
            for (int w = 1; w < 8; w++) bb = umin64(bb, swin[w]);
            sbest = bb;
            g_knn[i*KK + r] = (int)(bb & 0xFFFFFFFFu);
        }
        __syncthreads();
        unsigned long long best = sbest;
        if (lmin == best){                       // unique key (idx embedded): one owner
            #pragma unroll
            for (int m = 0; m < 16; m++) if (lk[m] == best) lk[m] = ~0ULL;
            lmin = lk[0];
            #pragma unroll
            for (int m = 1; m < 16; m++) lmin = umin64(lmin, lk[m]);
        }
        __syncthreads();
    }
}

// ---------------- K8: triangles, warp per pair (XLA matvec reduce for hf@wf2) ----------------
__global__ void __launch_bounds__(256) k_tri(const float* __restrict__ bf1,
                      const float* __restrict__ wf2,
                      float* __restrict__ out){
    __shared__ int   sk[KK];
    __shared__ float sAi[KK];
    __shared__ float sGi[HH];
    __shared__ float sGn[KK][HH+4];              // padded to dodge bank conflicts
    __shared__ float sb[HH], sw[HH];
    int i = blockIdx.x, t = threadIdx.x;         // 256 threads, 8 warps
    int lane = t & 31, warp = t >> 5;
    if (t < KK) sk[t] = g_knn[i*KK + t];
    if (t < HH){ sGi[t] = g_G[i*HH + t]; sb[t] = bf1[t]; sw[t] = wf2[t]; }
    __syncthreads();
    if (t < KK) sAi[t] = g_adj[i*NS + sk[t]];
    for (int q = warp; q < KK; q += 8){
        sGn[q][lane]      = g_G[sk[q]*HH + lane];
        sGn[q][lane+32]   = g_G[sk[q]*HH + lane + 32];
        sGn[q][lane+64]   = g_G[sk[q]*HH + lane + 64];
        sGn[q][lane+96]   = g_G[sk[q]*HH + lane + 96];
    }
    __syncthreads();
    const float third = 1.0f/3.0f;
    #pragma unroll
    for (int it = 0; it < NPAIR/8; it++){        // 15 iterations x 8 warps = 120 pairs
        int p0 = it*8 + warp;
        int p = p0, j = 0;
        while (p >= (KK - 1 - j)){ p -= (KK - 1 - j); j++; }   // triu_indices(16,1) order
        int l = j + 1 + p;
        // hf@wf2: lane partials k=lane+32m (rounded products, sequential adds), butterfly
        float s = 0.f;
        #pragma unroll
        for (int m = 0; m < 4; m++){
            int k = lane + 32*m;
            float pre = (sGi[k] + sGn[j][k] + sGn[l][k]) * third + sb[k];  // value-only path
            float hf  = fmaxf(pre, 0.f);
            s = __fadd_rn(s, __fmul_rn(hf, sw[k]));
        }
        s = warp_red_xla(s);
        if (lane == 0){
            int n1 = sk[j], n2 = sk[l];
            float a12  = g_adj[n1*NS + n2];
            bool valid = a12 > 0.f;
            float prod = __fmul_rn(__fmul_rn(sAi[j], sAi[l]), a12);
            float tpr  = valid ? cbrtf(fmaxf(prod, 1e-9f)) : 0.f;
            float fpr  = valid ? sigmoid_xla(s) : 0.f;
            out[i*NPAIR + p0]        = fpr;
            out[OUTM + i*NPAIR + p0] = tpr;
        }
    }
}

// ---------------- launch ----------------
extern "C" void kernel_launch(void* const* d_in, const int* in_sizes, int n_in,
                              void* d_out, int out_size){
    (void)in_sizes; (void)n_in; (void)out_size;
    const float* x   = (const float*)d_in[0];
    const float* pos = (const float*)d_in[1];
    const float* W1  = (const float*)d_in[2];
    const float* b1  = (const float*)d_in[3];
    const float* w2  = (const float*)d_in[4];
    const float* we  = (const float*)d_in[5];
    const float* Wf1 = (const float*)d_in[6];
    const float* bf1 = (const float*)d_in[7];
    const float* wf2 = (const float*)d_in[8];
    float* out = (float*)d_out;

    k_probs<<<NN/4, 128>>>(x, W1, b1, w2);       // idx 0
    k_rank_a<<<128, 256>>>();                    // idx 1
    k_sel_gather<<<NN/8, 256>>>(x, pos, Wf1);    // idx 2
    k_knn_pos<<<500, 256>>>();                   // idx 3  <- ncu verifies the rewrite
    k_zero_adj<<<1184, 256>>>();                 // idx 4
    k_edges<<<(NS*EK + 7)/8, 256>>>(we);         // idx 5
    k_nzlist<<<NS/8, 256>>>();                   // idx 6
    k_fd2knn<<<NS, 256>>>();                     // idx 7
    k_tri<<<NS, 256>>>(bf1, wf2, out);           // idx 8
}